// round 12
// baseline (speedup 1.0000x reference)
#include <cuda_runtime.h>
#include <math.h>
#include <stdint.h>

#define NIMG 8
#define CIN 256
#define HW 4096
#define NA 9
#define APIMG 36864
#define NPRE 6000
#define NPOST 300
#define KDIM 2304
#define NWORDS 94
#define KSTEPS 288

#define OFF_LOC   0
#define OFF_SCORE 1179648
#define OFF_ROIS  1769472
#define OFF_RIDX  1779072
#define OFF_ANCH  1781472

// ---------------- static device scratch ----------------
__device__ float g_wT[KDIM * 256];           // k-major weights [k=tap*256+c][oc]
__device__ float g_h[NIMG * CIN * HW];       // conv out NCHW
__device__ float g_boxes[NIMG * APIMG * 4];
__device__ unsigned g_key[NIMG * APIMG];
__device__ float g_top[NIMG * NPRE * 4];
__device__ unsigned long long g_mask[(size_t)NIMG * NPRE * NWORDS];

// ---------------- helpers ----------------
__device__ __forceinline__ unsigned long long pk2(float lo, float hi) {
    unsigned long long r;
    asm("mov.b64 %0, {%1, %2};" : "=l"(r) : "f"(lo), "f"(hi));
    return r;
}
__device__ __forceinline__ void fma2(unsigned long long& c, unsigned long long a,
                                     unsigned long long b) {
    asm("fma.rn.f32x2 %0, %1, %2, %0;" : "+l"(c) : "l"(a), "l"(b));
}
__device__ __forceinline__ void upk2(float& lo, float& hi, unsigned long long v) {
    asm("mov.b64 {%0, %1}, %2;" : "=f"(lo), "=f"(hi) : "l"(v));
}
__device__ __forceinline__ float read_dim(const void* p) {
    int v = *(const int*)p;
    if (v > 0 && v < 1048576) return (float)v;
    long long l = *(const long long*)p;
    if (l > 0 && l < 1048576) return (float)l;
    return *(const float*)p;
}

// ---------------- dummy kernel (shift k_conv into ncu's capture slot = 4th launch) ----------------
__global__ void k_nop() {}

// ---------------- K0: transpose conv1 weights to k-major (k = tap*256 + c) ----------------
__global__ void k_wt(const float* __restrict__ w) {
    int o = blockIdx.x;
    for (int k = threadIdx.x; k < KDIM; k += 256) {
        int c = k & 255;
        int tap = k >> 8;
        g_wT[(size_t)k * 256 + o] = w[(size_t)o * KDIM + c * 9 + tap];
    }
}

// ---------------- K1: conv3x3 SAME + bias + relu, implicit im2col, f32x2 FFMA2 ----------------
// 128x128 tile, 256 threads, 8x8 microtile (packed as 8x4 f32x2), BK=8,
// double-buffered smem with register prefetch. Bit-identical to FFMA ordering.
__global__ void __launch_bounds__(256, 2) k_conv(const float* __restrict__ x,
                                                 const float* __restrict__ bias) {
    __shared__ __align__(16) float As[2][8][128];
    __shared__ __align__(16) float Bs[2][8][128];
    const int m0 = blockIdx.x * 128;
    const int n0 = blockIdx.y * 128;
    const int tid = threadIdx.x;
    const int tx = tid & 15, ty = tid >> 4;

    const int ll = tid & 127;
    const int kb = tid >> 7;
    const int m = m0 + ll;
    const int nimg = m >> 12;
    const int p = m & 4095;
    const int yy = p >> 6, xx = p & 63;
    const float* xb = x + (((size_t)nimg * CIN) << 12);
    const float* wb = g_wT + (size_t)kb * 256 + n0 + ll;

    unsigned long long acc2[8][4];
#pragma unroll
    for (int i = 0; i < 8; i++)
#pragma unroll
        for (int j = 0; j < 4; j++) acc2[i][j] = 0ull;

    float va[4], vb[4];

#define LOADT(k0_)                                                              \
    {                                                                           \
        const int k0L = (k0_);                                                  \
        const int tapL = k0L >> 8;                                              \
        const int kyL = tapL / 3;                                               \
        const int kxL = tapL - kyL * 3;                                         \
        const int y2L = yy + kyL - 1, x2L = xx + kxL - 1;                       \
        const bool inbL = ((unsigned)y2L < 64u) && ((unsigned)x2L < 64u);       \
        const int aoffL = (((k0L & 255) + kb) << 12) + (y2L << 6) + x2L;        \
        const float* bpL = wb + (size_t)k0L * 256;                              \
        _Pragma("unroll")                                                       \
        for (int tL = 0; tL < 4; tL++) {                                        \
            va[tL] = inbL ? __ldg(xb + aoffL + (tL << 13)) : 0.f;               \
            vb[tL] = __ldg(bpL + (size_t)tL * 512);                             \
        }                                                                       \
    }

#define STORET(buf_)                                                            \
    {                                                                           \
        const int bfL = (buf_);                                                 \
        _Pragma("unroll")                                                       \
        for (int tL = 0; tL < 4; tL++) {                                        \
            As[bfL][kb + 2 * tL][ll] = va[tL];                                  \
            Bs[bfL][kb + 2 * tL][ll] = vb[tL];                                  \
        }                                                                       \
    }

    LOADT(0);
    STORET(0);
    __syncthreads();

    for (int s = 0; s < KSTEPS; s++) {
        const int cur = s & 1;
        if (s + 1 < KSTEPS) LOADT((s + 1) * 8);
#pragma unroll
        for (int kk = 0; kk < 8; kk++) {
            float4 a0 = ((const float4*)As[cur][kk])[ty * 2];
            float4 a1 = ((const float4*)As[cur][kk])[ty * 2 + 1];
            float4 b0 = ((const float4*)Bs[cur][kk])[tx * 2];
            float4 b1 = ((const float4*)Bs[cur][kk])[tx * 2 + 1];
            float av[8] = {a0.x, a0.y, a0.z, a0.w, a1.x, a1.y, a1.z, a1.w};
            unsigned long long b2[4] = {pk2(b0.x, b0.y), pk2(b0.z, b0.w),
                                        pk2(b1.x, b1.y), pk2(b1.z, b1.w)};
#pragma unroll
            for (int i2 = 0; i2 < 8; i2++) {
                unsigned long long a2 = pk2(av[i2], av[i2]);
#pragma unroll
                for (int j2 = 0; j2 < 4; j2++) fma2(acc2[i2][j2], a2, b2[j2]);
            }
        }
        if (s + 1 < KSTEPS) STORET((s + 1) & 1);
        __syncthreads();
    }
#undef LOADT
#undef STORET

    // epilogue: unpack + bias + relu -> g_h NCHW
#pragma unroll
    for (int i = 0; i < 8; i++) {
        int mo = m0 + ty * 8 + i;
        int n = mo >> 12;
        int pp = mo & 4095;
#pragma unroll
        for (int j2 = 0; j2 < 4; j2++) {
            float lo, hi;
            upk2(lo, hi, acc2[i][j2]);
            int o = n0 + tx * 8 + j2 * 2;
            g_h[(((size_t)n * CIN + o) << 12) + pp] = fmaxf(lo + bias[o], 0.f);
            g_h[(((size_t)n * CIN + o + 1) << 12) + pp] = fmaxf(hi + bias[o + 1], 0.f);
        }
    }
}

// ---------------- K2: fused 1x1 heads + softmax-fg + decode/clip/valid + keys ----------------
__global__ void __launch_bounds__(256) k_heads(const float* __restrict__ lw,
                                               const float* __restrict__ lb,
                                               const float* __restrict__ sw,
                                               const float* __restrict__ sb,
                                               float* __restrict__ out,
                                               const void* pih, const void* piw) {
    __shared__ float sh[4][256];
    __shared__ float so[4][56];
    int p0 = blockIdx.x * 4;
    int n = p0 >> 12;
    int pbase = p0 & 4095;
    for (int idx = threadIdx.x; idx < 1024; idx += 256) {
        int px = idx & 3;
        int c = idx >> 2;
        sh[px][c] = g_h[(((size_t)n * CIN + c) << 12) + pbase + px];
    }
    __syncthreads();
    {
        int px = threadIdx.x >> 6;
        int ch = threadIdx.x & 63;
        if (ch < 54) {
            const float* wv;
            float bv;
            if (ch < 36) { wv = lw + (size_t)ch * 256; bv = lb[ch]; }
            else         { wv = sw + (size_t)(ch - 36) * 256; bv = sb[ch - 36]; }
            float acc = 0.f;
#pragma unroll 8
            for (int k = 0; k < 256; k++) acc += sh[px][k] * wv[k];
            acc += bv;
            so[px][ch] = acc;
            int pp = (p0 + px) & 4095;
            if (ch < 36)
                out[OFF_LOC + (size_t)n * 147456 + (size_t)pp * 36 + ch] = acc;
            else
                out[OFF_SCORE + (size_t)n * 73728 + (size_t)pp * 18 + (ch - 36)] = acc;
        }
    }
    __syncthreads();
    if (threadIdx.x < 36) {
        int px = threadIdx.x / 9;
        int a = threadIdx.x % 9;
        int pp = (p0 + px) & 4095;
        int y = pp >> 6, xq = pp & 63;
        const double RAT[3] = {0.5, 1.0, 2.0};
        const double SCL[3] = {8.0, 16.0, 32.0};
        int ri = a / 3, sj = a % 3;
        double hh = 7.0 * SCL[sj] * sqrt(RAT[ri]);
        double wd = 7.0 * SCL[sj] * sqrt(1.0 / RAT[ri]);
        float ab0 = (float)(3.5 - hh / 2.0), ab1 = (float)(3.5 - wd / 2.0);
        float ab2 = (float)(3.5 + hh / 2.0), ab3 = (float)(3.5 + wd / 2.0);
        float shy = (float)(y * 16), shx = (float)(xq * 16);
        float A0 = shy + ab0, A1 = shx + ab1, A2 = shy + ab2, A3 = shx + ab3;
        long aidx = (long)pp * NA + a;
        if (n == 0) {
            float* ao = out + OFF_ANCH + (size_t)aidx * 4;
            ao[0] = A0; ao[1] = A1; ao[2] = A2; ao[3] = A3;
        }
        float ah = A2 - A0, aw = A3 - A1;
        float acy = A0 + 0.5f * ah, acx = A1 + 0.5f * aw;
        float dy = so[px][a * 4 + 0], dx = so[px][a * 4 + 1];
        float dh = so[px][a * 4 + 2], dw = so[px][a * 4 + 3];
        float cy = dy * ah + acy;
        float cx = dx * aw + acx;
        float bh = expf(dh) * ah;
        float bw = expf(dw) * aw;
        float imh = read_dim(pih), imw = read_dim(piw);
        float y1 = fminf(fmaxf(cy - 0.5f * bh, 0.f), imh);
        float x1 = fminf(fmaxf(cx - 0.5f * bw, 0.f), imw);
        float y2 = fminf(fmaxf(cy + 0.5f * bh, 0.f), imh);
        float x2 = fminf(fmaxf(cx + 0.5f * bw, 0.f), imw);
        bool valid = ((y2 - y1) >= 16.f) && ((x2 - x1) >= 16.f);
        float s0 = so[px][36 + 2 * a], s1 = so[px][37 + 2 * a];
        float mm = fmaxf(s0, s1);
        float e0 = expf(s0 - mm), e1 = expf(s1 - mm);
        float fg = __fdiv_rn(e1, __fadd_rn(e0, e1));
        float sc = valid ? fg : -INFINITY;
        unsigned u = __float_as_uint(sc);
        unsigned sbits = (u & 0x80000000u) ? ~u : (u | 0x80000000u);
        size_t gi = (size_t)n * APIMG + aidx;
        g_key[gi] = ~sbits;
        float* bp = g_boxes + gi * 4;
        bp[0] = y1; bp[1] = x1; bp[2] = y2; bp[3] = x2;
    }
}

// ---------------- K3: exact top-6000 (radix select + bitonic sort) ----------------
__global__ void __launch_bounds__(1024) k_topk() {
    extern __shared__ unsigned smem[];
    unsigned* keys = smem;
    unsigned long long* buf = (unsigned long long*)(smem + APIMG);
    __shared__ int hist[256];
    __shared__ unsigned s_val;
    __shared__ int s_rem;
    __shared__ int s_cnt;
    int n = blockIdx.x;
    int tid = threadIdx.x;
    const unsigned* gk = g_key + (size_t)n * APIMG;
    for (int i = tid; i < APIMG; i += 1024) keys[i] = gk[i];
    __syncthreads();

    unsigned prefix = 0, mask = 0;
    int rem = NPRE;
    for (int pass = 0; pass < 4; pass++) {
        int shift = 24 - pass * 8;
        if (tid < 256) hist[tid] = 0;
        __syncthreads();
        for (int i = tid; i < APIMG; i += 1024) {
            unsigned k = keys[i];
            if ((k & mask) == prefix) atomicAdd(&hist[(k >> shift) & 255], 1);
        }
        __syncthreads();
        if (tid == 0) {
            int accu = 0;
            for (int d = 0; d < 256; d++) {
                int c = hist[d];
                if (accu + c >= rem) { s_val = prefix | ((unsigned)d << shift); s_rem = rem - accu; break; }
                accu += c;
            }
        }
        __syncthreads();
        prefix = s_val;
        rem = s_rem;
        mask |= (0xFFu << shift);
    }
    unsigned T = prefix;
    int r = rem;

    unsigned ipref = 0, im = 0;
    int ir = r;
    for (int pass = 0; pass < 2; pass++) {
        int shift = 8 - pass * 8;
        if (tid < 256) hist[tid] = 0;
        __syncthreads();
        for (int i = tid; i < APIMG; i += 1024) {
            if (keys[i] == T && (((unsigned)i & im) == ipref))
                atomicAdd(&hist[((unsigned)i >> shift) & 255], 1);
        }
        __syncthreads();
        if (tid == 0) {
            int accu = 0;
            for (int d = 0; d < 256; d++) {
                int c = hist[d];
                if (accu + c >= ir) { s_val = ipref | ((unsigned)d << shift); s_rem = ir - accu; break; }
                accu += c;
            }
        }
        __syncthreads();
        ipref = s_val;
        ir = s_rem;
        im |= (0xFFu << shift);
    }
    unsigned idxT = ipref;

    if (tid == 0) s_cnt = 0;
    __syncthreads();
    for (int i = tid; i < APIMG; i += 1024) {
        unsigned k = keys[i];
        if (k < T || (k == T && (unsigned)i <= idxT)) {
            int pos = atomicAdd(&s_cnt, 1);
            buf[pos] = (((unsigned long long)k) << 32) | (unsigned)i;
        }
    }
    __syncthreads();
    int cnt = s_cnt;
    for (int i = tid; i < 8192; i += 1024)
        if (i >= cnt) buf[i] = 0xFFFFFFFFFFFFFFFFull;
    __syncthreads();
    for (int size = 2; size <= 8192; size <<= 1) {
        for (int stride = size >> 1; stride > 0; stride >>= 1) {
            for (int i = tid; i < 8192; i += 1024) {
                int ixj = i ^ stride;
                if (ixj > i) {
                    bool up = ((i & size) == 0);
                    unsigned long long vaa = buf[i], vbb = buf[ixj];
                    if ((vaa > vbb) == up) { buf[i] = vbb; buf[ixj] = vaa; }
                }
            }
            __syncthreads();
        }
    }
    for (int r2 = tid; r2 < NPRE; r2 += 1024) {
        unsigned idx = (unsigned)(buf[r2] & 0xFFFFFFFFull);
        float4 bb = *(const float4*)(g_boxes + ((size_t)n * APIMG + idx) * 4);
        *(float4*)(g_top + ((size_t)n * NPRE + r2) * 4) = bb;
    }
}

// ---------------- K4: NMS bitmask (upper triangle) ----------------
__global__ void __launch_bounds__(64) k_mask() {
    int n = blockIdx.z;
    int it = blockIdx.x, jt = blockIdx.y;
    if (jt < it) return;
    __shared__ float4 sb[64];
    __shared__ float sarea[64];
    int tid = threadIdx.x;
    int j = jt * 64 + tid;
    float4 bj = (j < NPRE) ? *(const float4*)(g_top + ((size_t)n * NPRE + j) * 4)
                           : make_float4(0, 0, 0, 0);
    sb[tid] = bj;
    sarea[tid] = (bj.z - bj.x) * (bj.w - bj.y);
    __syncthreads();
    int i = it * 64 + tid;
    if (i >= NPRE) return;
    float4 bi = *(const float4*)(g_top + ((size_t)n * NPRE + i) * 4);
    float ai = (bi.z - bi.x) * (bi.w - bi.y);
    unsigned long long bits = 0;
    int jmax = min(64, NPRE - jt * 64);
#pragma unroll 4
    for (int q = 0; q < 64; q++) {
        if (q < jmax) {
            float4 b2 = sb[q];
            float ty0 = fmaxf(bi.x, b2.x), tx0 = fmaxf(bi.y, b2.y);
            float by0 = fminf(bi.z, b2.z), bx0 = fminf(bi.w, b2.w);
            float ih = fmaxf(by0 - ty0, 0.f), iw = fmaxf(bx0 - tx0, 0.f);
            float inter = ih * iw;
            float iou = inter / (ai + sarea[q] - inter + 1e-9f);
            if (iou > 0.7f) bits |= (1ull << q);
        }
    }
    g_mask[((size_t)n * NPRE + i) * NWORDS + jt] = bits;
}

// ---------------- K5: sequential suppression + ROI writeout ----------------
__global__ void __launch_bounds__(32) k_nms(float* __restrict__ out) {
    int n = blockIdx.x;
    int lane = threadIdx.x;
    __shared__ int s_keep[NPOST];
    __shared__ int s_cnt;
    unsigned long long remv0 = 0, remv1 = 0, remv2 = 0;
    int cnt = 0;
    const unsigned long long* mbase = g_mask + (size_t)n * NPRE * NWORDS;
    for (int w = 0; w < NWORDS && cnt < NPOST; w++) {
        int owner = w & 31, slot = w >> 5;
        unsigned long long myv = (slot == 0) ? remv0 : ((slot == 1) ? remv1 : remv2);
        unsigned long long cur = __shfl_sync(0xffffffffu, myv, owner);
        int bmax = min(64, NPRE - (w << 6));
        for (int b = 0; b < bmax; b++) {
            if (!((cur >> b) & 1ull)) {
                int i = (w << 6) + b;
                if (lane == 0) s_keep[cnt] = i;
                cnt++;
                const unsigned long long* row = mbase + (size_t)i * NWORDS;
                if (lane >= w && lane < NWORDS) remv0 |= __ldg(row + lane);
                if (lane + 32 >= w && lane + 32 < NWORDS) remv1 |= __ldg(row + lane + 32);
                if (lane + 64 >= w && lane + 64 < NWORDS) remv2 |= __ldg(row + lane + 64);
                if (cnt >= NPOST) break;
                myv = (slot == 0) ? remv0 : ((slot == 1) ? remv1 : remv2);
                cur |= __shfl_sync(0xffffffffu, myv, owner);
            }
        }
    }
    if (lane == 0) s_cnt = cnt;
    __syncwarp();
    if (lane == 0 && cnt < NPOST) {
        int ptr = 0, fill = cnt;
        for (int i = 0; i < NPRE && fill < NPOST; i++) {
            if (ptr < cnt && s_keep[ptr] == i) ptr++;
            else s_keep[fill++] = i;
        }
    }
    __syncwarp();
    for (int r2 = lane; r2 < NPOST; r2 += 32) {
        int idx = s_keep[r2];
        float4 bb = *(const float4*)(g_top + ((size_t)n * NPRE + idx) * 4);
        float* o = out + OFF_ROIS + ((size_t)n * NPOST + r2) * 4;
        o[0] = bb.x; o[1] = bb.y; o[2] = bb.z; o[3] = bb.w;
        out[OFF_RIDX + n * NPOST + r2] = (float)n;
    }
}

// ---------------- launch ----------------
extern "C" void kernel_launch(void* const* d_in, const int* in_sizes, int n_in,
                              void* d_out, int out_size) {
    const float* x  = (const float*)d_in[0];
    const float* w1 = (const float*)d_in[1];
    const float* b1 = (const float*)d_in[2];
    const float* sw = (const float*)d_in[3];
    const float* sb = (const float*)d_in[4];
    const float* lw = (const float*)d_in[5];
    const float* lb = (const float*)d_in[6];
    const void* pih = d_in[7];
    const void* piw = d_in[8];
    float* out = (float*)d_out;

    k_wt<<<256, 256>>>(w1);                 // launch 1
    k_nop<<<1, 32>>>();                     // launch 2
    k_nop<<<1, 32>>>();                     // launch 3
    k_conv<<<dim3(256, 2), 256>>>(x, b1);   // launch 4 -> ncu captures THIS
    k_heads<<<8192, 256>>>(lw, lb, sw, sb, out, pih, piw);
    cudaFuncSetAttribute(k_topk, cudaFuncAttributeMaxDynamicSharedMemorySize, 213504);
    k_topk<<<8, 1024, 212992>>>();
    k_mask<<<dim3(94, 94, 8), 64>>>();
    k_nms<<<8, 32>>>(out);
}

// round 13
// speedup vs baseline: 1.0720x; 1.0720x over previous
#include <cuda_runtime.h>
#include <math.h>
#include <stdint.h>

#define NIMG 8
#define CIN 256
#define HW 4096
#define NA 9
#define APIMG 36864
#define NPRE 6000
#define NPOST 300
#define KDIM 2304
#define NWORDS 94
#define KSTEPS 288

#define OFF_LOC   0
#define OFF_SCORE 1179648
#define OFF_ROIS  1769472
#define OFF_RIDX  1779072
#define OFF_ANCH  1781472

// ---------------- static device scratch ----------------
__device__ float g_wT[KDIM * 256];           // k-major weights [k=tap*256+c][oc]
__device__ float g_h[NIMG * CIN * HW];       // conv out NCHW
__device__ float g_boxes[NIMG * APIMG * 4];
__device__ unsigned g_key[NIMG * APIMG];
__device__ float g_top[NIMG * NPRE * 4];
__device__ unsigned long long g_mask[(size_t)NIMG * NPRE * NWORDS];

__device__ __forceinline__ float read_dim(const void* p) {
    int v = *(const int*)p;
    if (v > 0 && v < 1048576) return (float)v;
    long long l = *(const long long*)p;
    if (l > 0 && l < 1048576) return (float)l;
    return *(const float*)p;
}

// ---------------- dummy kernel (keep k_conv in ncu's capture slot = 4th launch) ----------------
__global__ void k_nop() {}

// ---------------- K0: transpose conv1 weights to k-major (k = tap*256 + c) ----------------
__global__ void k_wt(const float* __restrict__ w) {
    int o = blockIdx.x;
    for (int k = threadIdx.x; k < KDIM; k += 256) {
        int c = k & 255;
        int tap = k >> 8;
        g_wT[(size_t)k * 256 + o] = w[(size_t)o * KDIM + c * 9 + tap];
    }
}

// ---------------- K1: conv3x3 SAME + bias + relu, implicit im2col FFMA SGEMM ----------------
// CTA 128pix x 64oc, grid (256,4), 256 threads, 8x4 microtile, BK=8,
// double-buffered smem + register prefetch. Per-output accumulation order
// identical to R2/R11 (ascending k) -> bit-identical results.
__global__ void __launch_bounds__(256, 3) k_conv(const float* __restrict__ x,
                                                 const float* __restrict__ bias) {
    __shared__ __align__(16) float As[2][8][128];
    __shared__ __align__(16) float Bs[2][8][64];
    const int m0 = blockIdx.x * 128;
    const int n0 = blockIdx.y * 64;
    const int tid = threadIdx.x;
    const int lane = tid & 31, wid = tid >> 5;
    const int wm = wid & 3, wn = wid >> 2;          // warp tile 32x32
    const int ty2 = lane >> 3, tx2 = lane & 7;      // thread tile 8x4

    // A loader: same geometry as R2 (pixel ll, k-row kb+2t)
    const int ll = tid & 127;
    const int kb = tid >> 7;
    const int m = m0 + ll;
    const int nimg = m >> 12;
    const int p = m & 4095;
    const int yy = p >> 6, xx = p & 63;
    const float* xb = x + (((size_t)nimg * CIN) << 12);
    // B loader: element e = tid + 256*t (t<2), row e>>6, col e&63
    const int brow0 = tid >> 6;          // 0..3
    const int bcol = tid & 63;
    const float* wb = g_wT + n0 + bcol;

    float acc[8][4];
#pragma unroll
    for (int i = 0; i < 8; i++)
#pragma unroll
        for (int j = 0; j < 4; j++) acc[i][j] = 0.f;

    float va[4], vb[2];

#define LOADT(k0_)                                                              \
    {                                                                           \
        const int k0L = (k0_);                                                  \
        const int tapL = k0L >> 8;                                              \
        const int kyL = tapL / 3;                                               \
        const int kxL = tapL - kyL * 3;                                         \
        const int y2L = yy + kyL - 1, x2L = xx + kxL - 1;                       \
        const bool inbL = ((unsigned)y2L < 64u) && ((unsigned)x2L < 64u);       \
        const int aoffL = (((k0L & 255) + kb) << 12) + (y2L << 6) + x2L;        \
        _Pragma("unroll")                                                       \
        for (int tL = 0; tL < 4; tL++)                                          \
            va[tL] = inbL ? __ldg(xb + aoffL + (tL << 13)) : 0.f;               \
        _Pragma("unroll")                                                       \
        for (int tL = 0; tL < 2; tL++)                                          \
            vb[tL] = __ldg(wb + (size_t)(k0L + brow0 + 4 * tL) * 256);          \
    }

#define STORET(buf_)                                                            \
    {                                                                           \
        const int bfL = (buf_);                                                 \
        _Pragma("unroll")                                                       \
        for (int tL = 0; tL < 4; tL++)                                          \
            As[bfL][kb + 2 * tL][ll] = va[tL];                                  \
        _Pragma("unroll")                                                       \
        for (int tL = 0; tL < 2; tL++)                                          \
            Bs[bfL][brow0 + 4 * tL][bcol] = vb[tL];                             \
    }

    LOADT(0);
    STORET(0);
    __syncthreads();

    const int arow = wm * 32 + ty2 * 8;
    const int brow = wn * 32 + tx2 * 4;

    for (int s = 0; s < KSTEPS; s++) {
        const int cur = s & 1;
        if (s + 1 < KSTEPS) LOADT((s + 1) * 8);
#pragma unroll
        for (int kk = 0; kk < 8; kk++) {
            float4 a0 = *(const float4*)&As[cur][kk][arow];
            float4 a1 = *(const float4*)&As[cur][kk][arow + 4];
            float4 b0 = *(const float4*)&Bs[cur][kk][brow];
            float av[8] = {a0.x, a0.y, a0.z, a0.w, a1.x, a1.y, a1.z, a1.w};
            float bv[4] = {b0.x, b0.y, b0.z, b0.w};
#pragma unroll
            for (int i2 = 0; i2 < 8; i2++)
#pragma unroll
                for (int j2 = 0; j2 < 4; j2++)
                    acc[i2][j2] += av[i2] * bv[j2];
        }
        if (s + 1 < KSTEPS) STORET((s + 1) & 1);
        __syncthreads();
    }
#undef LOADT
#undef STORET

    // epilogue: bias + relu -> g_h NCHW
#pragma unroll
    for (int i = 0; i < 8; i++) {
        int mo = m0 + arow + i;
        int n = mo >> 12;
        int pp = mo & 4095;
#pragma unroll
        for (int j = 0; j < 4; j++) {
            int o = n0 + brow + j;
            g_h[(((size_t)n * CIN + o) << 12) + pp] = fmaxf(acc[i][j] + bias[o], 0.f);
        }
    }
}

// ---------------- K2: fused 1x1 heads + softmax-fg + decode/clip/valid + keys ----------------
__global__ void __launch_bounds__(256) k_heads(const float* __restrict__ lw,
                                               const float* __restrict__ lb,
                                               const float* __restrict__ sw,
                                               const float* __restrict__ sb,
                                               float* __restrict__ out,
                                               const void* pih, const void* piw) {
    __shared__ float sh[4][256];
    __shared__ float so[4][56];
    int p0 = blockIdx.x * 4;
    int n = p0 >> 12;
    int pbase = p0 & 4095;
    for (int idx = threadIdx.x; idx < 1024; idx += 256) {
        int px = idx & 3;
        int c = idx >> 2;
        sh[px][c] = g_h[(((size_t)n * CIN + c) << 12) + pbase + px];
    }
    __syncthreads();
    {
        int px = threadIdx.x >> 6;
        int ch = threadIdx.x & 63;
        if (ch < 54) {
            const float* wv;
            float bv;
            if (ch < 36) { wv = lw + (size_t)ch * 256; bv = lb[ch]; }
            else         { wv = sw + (size_t)(ch - 36) * 256; bv = sb[ch - 36]; }
            float acc = 0.f;
#pragma unroll 8
            for (int k = 0; k < 256; k++) acc += sh[px][k] * wv[k];
            acc += bv;
            so[px][ch] = acc;
            int pp = (p0 + px) & 4095;
            if (ch < 36)
                out[OFF_LOC + (size_t)n * 147456 + (size_t)pp * 36 + ch] = acc;
            else
                out[OFF_SCORE + (size_t)n * 73728 + (size_t)pp * 18 + (ch - 36)] = acc;
        }
    }
    __syncthreads();
    if (threadIdx.x < 36) {
        int px = threadIdx.x / 9;
        int a = threadIdx.x % 9;
        int pp = (p0 + px) & 4095;
        int y = pp >> 6, xq = pp & 63;
        const double RAT[3] = {0.5, 1.0, 2.0};
        const double SCL[3] = {8.0, 16.0, 32.0};
        int ri = a / 3, sj = a % 3;
        double hh = 7.0 * SCL[sj] * sqrt(RAT[ri]);
        double wd = 7.0 * SCL[sj] * sqrt(1.0 / RAT[ri]);
        float ab0 = (float)(3.5 - hh / 2.0), ab1 = (float)(3.5 - wd / 2.0);
        float ab2 = (float)(3.5 + hh / 2.0), ab3 = (float)(3.5 + wd / 2.0);
        float shy = (float)(y * 16), shx = (float)(xq * 16);
        float A0 = shy + ab0, A1 = shx + ab1, A2 = shy + ab2, A3 = shx + ab3;
        long aidx = (long)pp * NA + a;
        if (n == 0) {
            float* ao = out + OFF_ANCH + (size_t)aidx * 4;
            ao[0] = A0; ao[1] = A1; ao[2] = A2; ao[3] = A3;
        }
        float ah = A2 - A0, aw = A3 - A1;
        float acy = A0 + 0.5f * ah, acx = A1 + 0.5f * aw;
        float dy = so[px][a * 4 + 0], dx = so[px][a * 4 + 1];
        float dh = so[px][a * 4 + 2], dw = so[px][a * 4 + 3];
        float cy = dy * ah + acy;
        float cx = dx * aw + acx;
        float bh = expf(dh) * ah;
        float bw = expf(dw) * aw;
        float imh = read_dim(pih), imw = read_dim(piw);
        float y1 = fminf(fmaxf(cy - 0.5f * bh, 0.f), imh);
        float x1 = fminf(fmaxf(cx - 0.5f * bw, 0.f), imw);
        float y2 = fminf(fmaxf(cy + 0.5f * bh, 0.f), imh);
        float x2 = fminf(fmaxf(cx + 0.5f * bw, 0.f), imw);
        bool valid = ((y2 - y1) >= 16.f) && ((x2 - x1) >= 16.f);
        float s0 = so[px][36 + 2 * a], s1 = so[px][37 + 2 * a];
        float mm = fmaxf(s0, s1);
        float e0 = expf(s0 - mm), e1 = expf(s1 - mm);
        float fg = __fdiv_rn(e1, __fadd_rn(e0, e1));
        float sc = valid ? fg : -INFINITY;
        unsigned u = __float_as_uint(sc);
        unsigned sbits = (u & 0x80000000u) ? ~u : (u | 0x80000000u);
        size_t gi = (size_t)n * APIMG + aidx;
        g_key[gi] = ~sbits;
        float* bp = g_boxes + gi * 4;
        bp[0] = y1; bp[1] = x1; bp[2] = y2; bp[3] = x2;
    }
}

// ---------------- K3: exact top-6000 (radix select + bitonic sort) ----------------
__global__ void __launch_bounds__(1024) k_topk() {
    extern __shared__ unsigned smem[];
    unsigned* keys = smem;
    unsigned long long* buf = (unsigned long long*)(smem + APIMG);
    __shared__ int hist[256];
    __shared__ unsigned s_val;
    __shared__ int s_rem;
    __shared__ int s_cnt;
    int n = blockIdx.x;
    int tid = threadIdx.x;
    const unsigned* gk = g_key + (size_t)n * APIMG;
    for (int i = tid; i < APIMG; i += 1024) keys[i] = gk[i];
    __syncthreads();

    unsigned prefix = 0, mask = 0;
    int rem = NPRE;
    for (int pass = 0; pass < 4; pass++) {
        int shift = 24 - pass * 8;
        if (tid < 256) hist[tid] = 0;
        __syncthreads();
        for (int i = tid; i < APIMG; i += 1024) {
            unsigned k = keys[i];
            if ((k & mask) == prefix) atomicAdd(&hist[(k >> shift) & 255], 1);
        }
        __syncthreads();
        if (tid == 0) {
            int accu = 0;
            for (int d = 0; d < 256; d++) {
                int c = hist[d];
                if (accu + c >= rem) { s_val = prefix | ((unsigned)d << shift); s_rem = rem - accu; break; }
                accu += c;
            }
        }
        __syncthreads();
        prefix = s_val;
        rem = s_rem;
        mask |= (0xFFu << shift);
    }
    unsigned T = prefix;
    int r = rem;

    unsigned ipref = 0, im = 0;
    int ir = r;
    for (int pass = 0; pass < 2; pass++) {
        int shift = 8 - pass * 8;
        if (tid < 256) hist[tid] = 0;
        __syncthreads();
        for (int i = tid; i < APIMG; i += 1024) {
            if (keys[i] == T && (((unsigned)i & im) == ipref))
                atomicAdd(&hist[((unsigned)i >> shift) & 255], 1);
        }
        __syncthreads();
        if (tid == 0) {
            int accu = 0;
            for (int d = 0; d < 256; d++) {
                int c = hist[d];
                if (accu + c >= ir) { s_val = ipref | ((unsigned)d << shift); s_rem = ir - accu; break; }
                accu += c;
            }
        }
        __syncthreads();
        ipref = s_val;
        ir = s_rem;
        im |= (0xFFu << shift);
    }
    unsigned idxT = ipref;

    if (tid == 0) s_cnt = 0;
    __syncthreads();
    for (int i = tid; i < APIMG; i += 1024) {
        unsigned k = keys[i];
        if (k < T || (k == T && (unsigned)i <= idxT)) {
            int pos = atomicAdd(&s_cnt, 1);
            buf[pos] = (((unsigned long long)k) << 32) | (unsigned)i;
        }
    }
    __syncthreads();
    int cnt = s_cnt;
    for (int i = tid; i < 8192; i += 1024)
        if (i >= cnt) buf[i] = 0xFFFFFFFFFFFFFFFFull;
    __syncthreads();
    for (int size = 2; size <= 8192; size <<= 1) {
        for (int stride = size >> 1; stride > 0; stride >>= 1) {
            for (int i = tid; i < 8192; i += 1024) {
                int ixj = i ^ stride;
                if (ixj > i) {
                    bool up = ((i & size) == 0);
                    unsigned long long vaa = buf[i], vbb = buf[ixj];
                    if ((vaa > vbb) == up) { buf[i] = vbb; buf[ixj] = vaa; }
                }
            }
            __syncthreads();
        }
    }
    for (int r2 = tid; r2 < NPRE; r2 += 1024) {
        unsigned idx = (unsigned)(buf[r2] & 0xFFFFFFFFull);
        float4 bb = *(const float4*)(g_boxes + ((size_t)n * APIMG + idx) * 4);
        *(float4*)(g_top + ((size_t)n * NPRE + r2) * 4) = bb;
    }
}

// ---------------- K4: NMS bitmask (upper triangle) ----------------
__global__ void __launch_bounds__(64) k_mask() {
    int n = blockIdx.z;
    int it = blockIdx.x, jt = blockIdx.y;
    if (jt < it) return;
    __shared__ float4 sb[64];
    __shared__ float sarea[64];
    int tid = threadIdx.x;
    int j = jt * 64 + tid;
    float4 bj = (j < NPRE) ? *(const float4*)(g_top + ((size_t)n * NPRE + j) * 4)
                           : make_float4(0, 0, 0, 0);
    sb[tid] = bj;
    sarea[tid] = (bj.z - bj.x) * (bj.w - bj.y);
    __syncthreads();
    int i = it * 64 + tid;
    if (i >= NPRE) return;
    float4 bi = *(const float4*)(g_top + ((size_t)n * NPRE + i) * 4);
    float ai = (bi.z - bi.x) * (bi.w - bi.y);
    unsigned long long bits = 0;
    int jmax = min(64, NPRE - jt * 64);
#pragma unroll 4
    for (int q = 0; q < 64; q++) {
        if (q < jmax) {
            float4 b2 = sb[q];
            float ty0 = fmaxf(bi.x, b2.x), tx0 = fmaxf(bi.y, b2.y);
            float by0 = fminf(bi.z, b2.z), bx0 = fminf(bi.w, b2.w);
            float ih = fmaxf(by0 - ty0, 0.f), iw = fmaxf(bx0 - tx0, 0.f);
            float inter = ih * iw;
            float iou = inter / (ai + sarea[q] - inter + 1e-9f);
            if (iou > 0.7f) bits |= (1ull << q);
        }
    }
    g_mask[((size_t)n * NPRE + i) * NWORDS + jt] = bits;
}

// ---------------- K5: sequential suppression + ROI writeout ----------------
__global__ void __launch_bounds__(32) k_nms(float* __restrict__ out) {
    int n = blockIdx.x;
    int lane = threadIdx.x;
    __shared__ int s_keep[NPOST];
    __shared__ int s_cnt;
    unsigned long long remv0 = 0, remv1 = 0, remv2 = 0;
    int cnt = 0;
    const unsigned long long* mbase = g_mask + (size_t)n * NPRE * NWORDS;
    for (int w = 0; w < NWORDS && cnt < NPOST; w++) {
        int owner = w & 31, slot = w >> 5;
        unsigned long long myv = (slot == 0) ? remv0 : ((slot == 1) ? remv1 : remv2);
        unsigned long long cur = __shfl_sync(0xffffffffu, myv, owner);
        int bmax = min(64, NPRE - (w << 6));
        for (int b = 0; b < bmax; b++) {
            if (!((cur >> b) & 1ull)) {
                int i = (w << 6) + b;
                if (lane == 0) s_keep[cnt] = i;
                cnt++;
                const unsigned long long* row = mbase + (size_t)i * NWORDS;
                if (lane >= w && lane < NWORDS) remv0 |= __ldg(row + lane);
                if (lane + 32 >= w && lane + 32 < NWORDS) remv1 |= __ldg(row + lane + 32);
                if (lane + 64 >= w && lane + 64 < NWORDS) remv2 |= __ldg(row + lane + 64);
                if (cnt >= NPOST) break;
                myv = (slot == 0) ? remv0 : ((slot == 1) ? remv1 : remv2);
                cur |= __shfl_sync(0xffffffffu, myv, owner);
            }
        }
    }
    if (lane == 0) s_cnt = cnt;
    __syncwarp();
    if (lane == 0 && cnt < NPOST) {
        int ptr = 0, fill = cnt;
        for (int i = 0; i < NPRE && fill < NPOST; i++) {
            if (ptr < cnt && s_keep[ptr] == i) ptr++;
            else s_keep[fill++] = i;
        }
    }
    __syncwarp();
    for (int r2 = lane; r2 < NPOST; r2 += 32) {
        int idx = s_keep[r2];
        float4 bb = *(const float4*)(g_top + ((size_t)n * NPRE + idx) * 4);
        float* o = out + OFF_ROIS + ((size_t)n * NPOST + r2) * 4;
        o[0] = bb.x; o[1] = bb.y; o[2] = bb.z; o[3] = bb.w;
        out[OFF_RIDX + n * NPOST + r2] = (float)n;
    }
}

// ---------------- launch ----------------
extern "C" void kernel_launch(void* const* d_in, const int* in_sizes, int n_in,
                              void* d_out, int out_size) {
    const float* x  = (const float*)d_in[0];
    const float* w1 = (const float*)d_in[1];
    const float* b1 = (const float*)d_in[2];
    const float* sw = (const float*)d_in[3];
    const float* sb = (const float*)d_in[4];
    const float* lw = (const float*)d_in[5];
    const float* lb = (const float*)d_in[6];
    const void* pih = d_in[7];
    const void* piw = d_in[8];
    float* out = (float*)d_out;

    k_wt<<<256, 256>>>(w1);                 // launch 1
    k_nop<<<1, 32>>>();                     // launch 2
    k_nop<<<1, 32>>>();                     // launch 3
    k_conv<<<dim3(256, 4), 256>>>(x, b1);   // launch 4 -> ncu captures THIS
    k_heads<<<8192, 256>>>(lw, lb, sw, sb, out, pih, piw);
    cudaFuncSetAttribute(k_topk, cudaFuncAttributeMaxDynamicSharedMemorySize, 213504);
    k_topk<<<8, 1024, 212992>>>();
    k_mask<<<dim3(94, 94, 8), 64>>>();
    k_nms<<<8, 32>>>(out);
}

// round 14
// speedup vs baseline: 2.0113x; 1.8762x over previous
#include <cuda_runtime.h>
#include <math.h>
#include <stdint.h>

#define NIMG 8
#define CIN 256
#define HW 4096
#define NA 9
#define APIMG 36864
#define NPRE 6000
#define NPOST 300
#define KDIM 2304
#define NWORDS 94
#define KSTEPS 288

#define OFF_LOC   0
#define OFF_SCORE 1179648
#define OFF_ROIS  1769472
#define OFF_RIDX  1779072
#define OFF_ANCH  1781472

// k_heads smem layout (floats)
#define WS_OFF 0            // ws[54][257]
#define HS_OFF 13878        // hs[32][257]
#define SO_OFF 22102        // so[32][56]
#define HEADS_SMEM_F 23894
#define HEADS_SMEM_B (HEADS_SMEM_F * 4)   // 95576

// ---------------- static device scratch ----------------
__device__ float g_wT[KDIM * 256];
__device__ float g_h[NIMG * CIN * HW];
__device__ float g_boxes[NIMG * APIMG * 4];
__device__ unsigned g_key[NIMG * APIMG];
__device__ float g_top[NIMG * NPRE * 4];
__device__ unsigned long long g_mask[(size_t)NIMG * NPRE * NWORDS];

__device__ __forceinline__ float read_dim(const void* p) {
    int v = *(const int*)p;
    if (v > 0 && v < 1048576) return (float)v;
    long long l = *(const long long*)p;
    if (l > 0 && l < 1048576) return (float)l;
    return *(const float*)p;
}

__global__ void k_nop() {}

// ---------------- K0: transpose conv1 weights to k-major ----------------
__global__ void k_wt(const float* __restrict__ w) {
    int o = blockIdx.x;
    for (int k = threadIdx.x; k < KDIM; k += 256) {
        int c = k & 255;
        int tap = k >> 8;
        g_wT[(size_t)k * 256 + o] = w[(size_t)o * KDIM + c * 9 + tap];
    }
}

// ---------------- K1: conv (unchanged from R13 best) ----------------
__global__ void __launch_bounds__(256, 3) k_conv(const float* __restrict__ x,
                                                 const float* __restrict__ bias) {
    __shared__ __align__(16) float As[2][8][128];
    __shared__ __align__(16) float Bs[2][8][64];
    const int m0 = blockIdx.x * 128;
    const int n0 = blockIdx.y * 64;
    const int tid = threadIdx.x;
    const int lane = tid & 31, wid = tid >> 5;
    const int wm = wid & 3, wn = wid >> 2;
    const int ty2 = lane >> 3, tx2 = lane & 7;

    const int ll = tid & 127;
    const int kb = tid >> 7;
    const int m = m0 + ll;
    const int nimg = m >> 12;
    const int p = m & 4095;
    const int yy = p >> 6, xx = p & 63;
    const float* xb = x + (((size_t)nimg * CIN) << 12);
    const int brow0 = tid >> 6;
    const int bcol = tid & 63;
    const float* wb = g_wT + n0 + bcol;

    float acc[8][4];
#pragma unroll
    for (int i = 0; i < 8; i++)
#pragma unroll
        for (int j = 0; j < 4; j++) acc[i][j] = 0.f;

    float va[4], vb[2];

#define LOADT(k0_)                                                              \
    {                                                                           \
        const int k0L = (k0_);                                                  \
        const int tapL = k0L >> 8;                                              \
        const int kyL = tapL / 3;                                               \
        const int kxL = tapL - kyL * 3;                                         \
        const int y2L = yy + kyL - 1, x2L = xx + kxL - 1;                       \
        const bool inbL = ((unsigned)y2L < 64u) && ((unsigned)x2L < 64u);       \
        const int aoffL = (((k0L & 255) + kb) << 12) + (y2L << 6) + x2L;        \
        _Pragma("unroll")                                                       \
        for (int tL = 0; tL < 4; tL++)                                          \
            va[tL] = inbL ? __ldg(xb + aoffL + (tL << 13)) : 0.f;               \
        _Pragma("unroll")                                                       \
        for (int tL = 0; tL < 2; tL++)                                          \
            vb[tL] = __ldg(wb + (size_t)(k0L + brow0 + 4 * tL) * 256);          \
    }

#define STORET(buf_)                                                            \
    {                                                                           \
        const int bfL = (buf_);                                                 \
        _Pragma("unroll")                                                       \
        for (int tL = 0; tL < 4; tL++)                                          \
            As[bfL][kb + 2 * tL][ll] = va[tL];                                  \
        _Pragma("unroll")                                                       \
        for (int tL = 0; tL < 2; tL++)                                          \
            Bs[bfL][brow0 + 4 * tL][bcol] = vb[tL];                             \
    }

    LOADT(0);
    STORET(0);
    __syncthreads();

    const int arow = wm * 32 + ty2 * 8;
    const int brow = wn * 32 + tx2 * 4;

    for (int s = 0; s < KSTEPS; s++) {
        const int cur = s & 1;
        if (s + 1 < KSTEPS) LOADT((s + 1) * 8);
#pragma unroll
        for (int kk = 0; kk < 8; kk++) {
            float4 a0 = *(const float4*)&As[cur][kk][arow];
            float4 a1 = *(const float4*)&As[cur][kk][arow + 4];
            float4 b0 = *(const float4*)&Bs[cur][kk][brow];
            float av[8] = {a0.x, a0.y, a0.z, a0.w, a1.x, a1.y, a1.z, a1.w};
            float bv[4] = {b0.x, b0.y, b0.z, b0.w};
#pragma unroll
            for (int i2 = 0; i2 < 8; i2++)
#pragma unroll
                for (int j2 = 0; j2 < 4; j2++)
                    acc[i2][j2] += av[i2] * bv[j2];
        }
        if (s + 1 < KSTEPS) STORET((s + 1) & 1);
        __syncthreads();
    }
#undef LOADT
#undef STORET

#pragma unroll
    for (int i = 0; i < 8; i++) {
        int mo = m0 + arow + i;
        int n = mo >> 12;
        int pp = mo & 4095;
#pragma unroll
        for (int j = 0; j < 4; j++) {
            int o = n0 + brow + j;
            g_h[(((size_t)n * CIN + o) << 12) + pp] = fmaxf(acc[i][j] + bias[o], 0.f);
        }
    }
}

// ---------------- K2: heads v2 — smem-cached weights, 32 pixels/block ----------------
__global__ void __launch_bounds__(256) k_heads(const float* __restrict__ lw,
                                               const float* __restrict__ lb,
                                               const float* __restrict__ sw,
                                               const float* __restrict__ sb,
                                               float* __restrict__ out,
                                               const void* pih, const void* piw) {
    extern __shared__ float sm[];
    float* ws = sm + WS_OFF;   // [54][257]
    float* hs = sm + HS_OFF;   // [32][257]
    float* so = sm + SO_OFF;   // [32][56]
    const int tid = threadIdx.x;
    const int p0 = blockIdx.x * 32;
    const int n = p0 >> 12;
    const int pbase = p0 & 4095;

    // load weights (54 x 256) into smem, padded stride 257
    for (int idx = tid; idx < 54 * 256; idx += 256) {
        int ch = idx >> 8, k = idx & 255;
        float v = (ch < 36) ? lw[ch * 256 + k] : sw[(ch - 36) * 256 + k];
        ws[ch * 257 + k] = v;
    }
    // load h tile (32 pixels x 256 ch), coalesced gmem reads
    for (int idx = tid; idx < 32 * 256; idx += 256) {
        int c = idx >> 5, px = idx & 31;
        hs[px * 257 + c] = g_h[(((size_t)n * CIN + c) << 12) + pbase + px];
    }
    __syncthreads();

    // compute: tasks = ch(0..63 pad) x pgroup(0..7 of 4 pixels)
    for (int round = 0; round < 2; round++) {
        int task = tid + round * 256;
        int ch = task & 63;
        int pg = task >> 6;
        if (ch < 54) {
            const float* wr = ws + ch * 257;
            const float* h0 = hs + (pg * 4 + 0) * 257;
            const float* h1 = hs + (pg * 4 + 1) * 257;
            const float* h2 = hs + (pg * 4 + 2) * 257;
            const float* h3 = hs + (pg * 4 + 3) * 257;
            float a0 = 0.f, a1 = 0.f, a2 = 0.f, a3 = 0.f;
#pragma unroll 4
            for (int k = 0; k < 256; k++) {
                float w = wr[k];
                a0 += w * h0[k];
                a1 += w * h1[k];
                a2 += w * h2[k];
                a3 += w * h3[k];
            }
            float bv = (ch < 36) ? lb[ch] : sb[ch - 36];
            float r[4] = {a0 + bv, a1 + bv, a2 + bv, a3 + bv};
#pragma unroll
            for (int j = 0; j < 4; j++) {
                int px = pg * 4 + j;
                int pp = pbase + px;
                so[px * 56 + ch] = r[j];
                if (ch < 36)
                    out[OFF_LOC + (size_t)n * 147456 + (size_t)pp * 36 + ch] = r[j];
                else
                    out[OFF_SCORE + (size_t)n * 73728 + (size_t)pp * 18 + (ch - 36)] = r[j];
            }
        }
    }
    __syncthreads();

    // anchor decode: 32 px x 9 anchors = 288 tasks
    const float imh = read_dim(pih), imw = read_dim(piw);
    for (int t = tid; t < 288; t += 256) {
        int px = t / 9;
        int a = t - px * 9;
        int pp = pbase + px;
        int y = pp >> 6, xq = pp & 63;
        const double RAT[3] = {0.5, 1.0, 2.0};
        const double SCL[3] = {8.0, 16.0, 32.0};
        int ri = a / 3, sj = a % 3;
        double hh = 7.0 * SCL[sj] * sqrt(RAT[ri]);
        double wd = 7.0 * SCL[sj] * sqrt(1.0 / RAT[ri]);
        float ab0 = (float)(3.5 - hh / 2.0), ab1 = (float)(3.5 - wd / 2.0);
        float ab2 = (float)(3.5 + hh / 2.0), ab3 = (float)(3.5 + wd / 2.0);
        float shy = (float)(y * 16), shx = (float)(xq * 16);
        float A0 = shy + ab0, A1 = shx + ab1, A2 = shy + ab2, A3 = shx + ab3;
        long aidx = (long)pp * NA + a;
        if (n == 0) {
            float* ao = out + OFF_ANCH + (size_t)aidx * 4;
            ao[0] = A0; ao[1] = A1; ao[2] = A2; ao[3] = A3;
        }
        float ah = A2 - A0, aw = A3 - A1;
        float acy = A0 + 0.5f * ah, acx = A1 + 0.5f * aw;
        const float* sop = so + px * 56;
        float dy = sop[a * 4 + 0], dx = sop[a * 4 + 1];
        float dh = sop[a * 4 + 2], dw = sop[a * 4 + 3];
        float cy = dy * ah + acy;
        float cx = dx * aw + acx;
        float bh = expf(dh) * ah;
        float bw = expf(dw) * aw;
        float y1 = fminf(fmaxf(cy - 0.5f * bh, 0.f), imh);
        float x1 = fminf(fmaxf(cx - 0.5f * bw, 0.f), imw);
        float y2 = fminf(fmaxf(cy + 0.5f * bh, 0.f), imh);
        float x2 = fminf(fmaxf(cx + 0.5f * bw, 0.f), imw);
        bool valid = ((y2 - y1) >= 16.f) && ((x2 - x1) >= 16.f);
        float s0 = sop[36 + 2 * a], s1 = sop[37 + 2 * a];
        float mm = fmaxf(s0, s1);
        float e0 = expf(s0 - mm), e1 = expf(s1 - mm);
        float fg = __fdiv_rn(e1, __fadd_rn(e0, e1));
        float sc = valid ? fg : -INFINITY;
        unsigned u = __float_as_uint(sc);
        unsigned sbits = (u & 0x80000000u) ? ~u : (u | 0x80000000u);
        size_t gi = (size_t)n * APIMG + aidx;
        g_key[gi] = ~sbits;
        float* bp = g_boxes + gi * 4;
        bp[0] = y1; bp[1] = x1; bp[2] = y2; bp[3] = x2;
    }
}

// ---------------- K3: exact top-6000 (radix select + bitonic sort) ----------------
__global__ void __launch_bounds__(1024) k_topk() {
    extern __shared__ unsigned smem[];
    unsigned* keys = smem;
    unsigned long long* buf = (unsigned long long*)(smem + APIMG);
    __shared__ int hist[256];
    __shared__ unsigned s_val;
    __shared__ int s_rem;
    __shared__ int s_cnt;
    int n = blockIdx.x;
    int tid = threadIdx.x;
    const unsigned* gk = g_key + (size_t)n * APIMG;
    for (int i = tid; i < APIMG; i += 1024) keys[i] = gk[i];
    __syncthreads();

    unsigned prefix = 0, mask = 0;
    int rem = NPRE;
    for (int pass = 0; pass < 4; pass++) {
        int shift = 24 - pass * 8;
        if (tid < 256) hist[tid] = 0;
        __syncthreads();
        for (int i = tid; i < APIMG; i += 1024) {
            unsigned k = keys[i];
            if ((k & mask) == prefix) atomicAdd(&hist[(k >> shift) & 255], 1);
        }
        __syncthreads();
        if (tid == 0) {
            int accu = 0;
            for (int d = 0; d < 256; d++) {
                int c = hist[d];
                if (accu + c >= rem) { s_val = prefix | ((unsigned)d << shift); s_rem = rem - accu; break; }
                accu += c;
            }
        }
        __syncthreads();
        prefix = s_val;
        rem = s_rem;
        mask |= (0xFFu << shift);
    }
    unsigned T = prefix;
    int r = rem;

    unsigned ipref = 0, im = 0;
    int ir = r;
    for (int pass = 0; pass < 2; pass++) {
        int shift = 8 - pass * 8;
        if (tid < 256) hist[tid] = 0;
        __syncthreads();
        for (int i = tid; i < APIMG; i += 1024) {
            if (keys[i] == T && (((unsigned)i & im) == ipref))
                atomicAdd(&hist[((unsigned)i >> shift) & 255], 1);
        }
        __syncthreads();
        if (tid == 0) {
            int accu = 0;
            for (int d = 0; d < 256; d++) {
                int c = hist[d];
                if (accu + c >= ir) { s_val = ipref | ((unsigned)d << shift); s_rem = ir - accu; break; }
                accu += c;
            }
        }
        __syncthreads();
        ipref = s_val;
        ir = s_rem;
        im |= (0xFFu << shift);
    }
    unsigned idxT = ipref;

    if (tid == 0) s_cnt = 0;
    __syncthreads();
    for (int i = tid; i < APIMG; i += 1024) {
        unsigned k = keys[i];
        if (k < T || (k == T && (unsigned)i <= idxT)) {
            int pos = atomicAdd(&s_cnt, 1);
            buf[pos] = (((unsigned long long)k) << 32) | (unsigned)i;
        }
    }
    __syncthreads();
    int cnt = s_cnt;
    for (int i = tid; i < 8192; i += 1024)
        if (i >= cnt) buf[i] = 0xFFFFFFFFFFFFFFFFull;
    __syncthreads();
    for (int size = 2; size <= 8192; size <<= 1) {
        for (int stride = size >> 1; stride > 0; stride >>= 1) {
            for (int i = tid; i < 8192; i += 1024) {
                int ixj = i ^ stride;
                if (ixj > i) {
                    bool up = ((i & size) == 0);
                    unsigned long long vaa = buf[i], vbb = buf[ixj];
                    if ((vaa > vbb) == up) { buf[i] = vbb; buf[ixj] = vaa; }
                }
            }
            __syncthreads();
        }
    }
    for (int r2 = tid; r2 < NPRE; r2 += 1024) {
        unsigned idx = (unsigned)(buf[r2] & 0xFFFFFFFFull);
        float4 bb = *(const float4*)(g_boxes + ((size_t)n * APIMG + idx) * 4);
        *(float4*)(g_top + ((size_t)n * NPRE + r2) * 4) = bb;
    }
}

// ---------------- K4: NMS bitmask (upper triangle) ----------------
__global__ void __launch_bounds__(64) k_mask() {
    int n = blockIdx.z;
    int it = blockIdx.x, jt = blockIdx.y;
    if (jt < it) return;
    __shared__ float4 sb[64];
    __shared__ float sarea[64];
    int tid = threadIdx.x;
    int j = jt * 64 + tid;
    float4 bj = (j < NPRE) ? *(const float4*)(g_top + ((size_t)n * NPRE + j) * 4)
                           : make_float4(0, 0, 0, 0);
    sb[tid] = bj;
    sarea[tid] = (bj.z - bj.x) * (bj.w - bj.y);
    __syncthreads();
    int i = it * 64 + tid;
    if (i >= NPRE) return;
    float4 bi = *(const float4*)(g_top + ((size_t)n * NPRE + i) * 4);
    float ai = (bi.z - bi.x) * (bi.w - bi.y);
    unsigned long long bits = 0;
    int jmax = min(64, NPRE - jt * 64);
#pragma unroll 4
    for (int q = 0; q < 64; q++) {
        if (q < jmax) {
            float4 b2 = sb[q];
            float ty0 = fmaxf(bi.x, b2.x), tx0 = fmaxf(bi.y, b2.y);
            float by0 = fminf(bi.z, b2.z), bx0 = fminf(bi.w, b2.w);
            float ih = fmaxf(by0 - ty0, 0.f), iw = fmaxf(bx0 - tx0, 0.f);
            float inter = ih * iw;
            float iou = inter / (ai + sarea[q] - inter + 1e-9f);
            if (iou > 0.7f) bits |= (1ull << q);
        }
    }
    g_mask[((size_t)n * NPRE + i) * NWORDS + jt] = bits;
}

// ---------------- K5: sequential suppression + ROI writeout ----------------
__global__ void __launch_bounds__(32) k_nms(float* __restrict__ out) {
    int n = blockIdx.x;
    int lane = threadIdx.x;
    __shared__ int s_keep[NPOST];
    __shared__ int s_cnt;
    unsigned long long remv0 = 0, remv1 = 0, remv2 = 0;
    int cnt = 0;
    const unsigned long long* mbase = g_mask + (size_t)n * NPRE * NWORDS;
    for (int w = 0; w < NWORDS && cnt < NPOST; w++) {
        int owner = w & 31, slot = w >> 5;
        unsigned long long myv = (slot == 0) ? remv0 : ((slot == 1) ? remv1 : remv2);
        unsigned long long cur = __shfl_sync(0xffffffffu, myv, owner);
        int bmax = min(64, NPRE - (w << 6));
        for (int b = 0; b < bmax; b++) {
            if (!((cur >> b) & 1ull)) {
                int i = (w << 6) + b;
                if (lane == 0) s_keep[cnt] = i;
                cnt++;
                const unsigned long long* row = mbase + (size_t)i * NWORDS;
                if (lane >= w && lane < NWORDS) remv0 |= __ldg(row + lane);
                if (lane + 32 >= w && lane + 32 < NWORDS) remv1 |= __ldg(row + lane + 32);
                if (lane + 64 >= w && lane + 64 < NWORDS) remv2 |= __ldg(row + lane + 64);
                if (cnt >= NPOST) break;
                myv = (slot == 0) ? remv0 : ((slot == 1) ? remv1 : remv2);
                cur |= __shfl_sync(0xffffffffu, myv, owner);
            }
        }
    }
    if (lane == 0) s_cnt = cnt;
    __syncwarp();
    if (lane == 0 && cnt < NPOST) {
        int ptr = 0, fill = cnt;
        for (int i = 0; i < NPRE && fill < NPOST; i++) {
            if (ptr < cnt && s_keep[ptr] == i) ptr++;
            else s_keep[fill++] = i;
        }
    }
    __syncwarp();
    for (int r2 = lane; r2 < NPOST; r2 += 32) {
        int idx = s_keep[r2];
        float4 bb = *(const float4*)(g_top + ((size_t)n * NPRE + idx) * 4);
        float* o = out + OFF_ROIS + ((size_t)n * NPOST + r2) * 4;
        o[0] = bb.x; o[1] = bb.y; o[2] = bb.z; o[3] = bb.w;
        out[OFF_RIDX + n * NPOST + r2] = (float)n;
    }
}

// ---------------- launch ----------------
extern "C" void kernel_launch(void* const* d_in, const int* in_sizes, int n_in,
                              void* d_out, int out_size) {
    const float* x  = (const float*)d_in[0];
    const float* w1 = (const float*)d_in[1];
    const float* b1 = (const float*)d_in[2];
    const float* sw = (const float*)d_in[3];
    const float* sb = (const float*)d_in[4];
    const float* lw = (const float*)d_in[5];
    const float* lb = (const float*)d_in[6];
    const void* pih = d_in[7];
    const void* piw = d_in[8];
    float* out = (float*)d_out;

    k_wt<<<256, 256>>>(w1);                 // launch 1
    k_nop<<<1, 32>>>();                     // launch 2
    k_conv<<<dim3(256, 4), 256>>>(x, b1);   // launch 3
    cudaFuncSetAttribute(k_heads, cudaFuncAttributeMaxDynamicSharedMemorySize, HEADS_SMEM_B);
    k_heads<<<1024, 256, HEADS_SMEM_B>>>(lw, lb, sw, sb, out, pih, piw);  // launch 4 -> ncu
    cudaFuncSetAttribute(k_topk, cudaFuncAttributeMaxDynamicSharedMemorySize, 213504);
    k_topk<<<8, 1024, 212992>>>();
    k_mask<<<dim3(94, 94, 8), 64>>>();
    k_nms<<<8, 32>>>(out);
}

// round 15
// speedup vs baseline: 2.1103x; 1.0492x over previous
#include <cuda_runtime.h>
#include <math.h>
#include <stdint.h>

#define NIMG 8
#define CIN 256
#define HW 4096
#define NA 9
#define APIMG 36864
#define NPRE 6000
#define NPOST 300
#define KDIM 2304
#define NWORDS 94
#define KSTEPS 288

#define OFF_LOC   0
#define OFF_SCORE 1179648
#define OFF_ROIS  1769472
#define OFF_RIDX  1779072
#define OFF_ANCH  1781472

#define WS_OFF 0
#define HS_OFF 13878
#define SO_OFF 22102
#define HEADS_SMEM_F 23894
#define HEADS_SMEM_B (HEADS_SMEM_F * 4)

// ---------------- static device scratch ----------------
__device__ float g_wT[KDIM * 256];
__device__ float g_h[NIMG * CIN * HW];
__device__ float g_boxes[NIMG * APIMG * 4];
__device__ unsigned g_key[NIMG * APIMG];
__device__ float g_top[NIMG * NPRE * 4];
__device__ unsigned long long g_mask[(size_t)NIMG * NPRE * NWORDS];

__device__ __forceinline__ unsigned long long pk2(float lo, float hi) {
    unsigned long long r;
    asm("mov.b64 %0, {%1, %2};" : "=l"(r) : "f"(lo), "f"(hi));
    return r;
}
__device__ __forceinline__ void fma2(unsigned long long& c, unsigned long long a,
                                     unsigned long long b) {
    asm("fma.rn.f32x2 %0, %1, %2, %0;" : "+l"(c) : "l"(a), "l"(b));
}
__device__ __forceinline__ void upk2(float& lo, float& hi, unsigned long long v) {
    asm("mov.b64 {%0, %1}, %2;" : "=f"(lo), "=f"(hi) : "l"(v));
}
__device__ __forceinline__ float read_dim(const void* p) {
    int v = *(const int*)p;
    if (v > 0 && v < 1048576) return (float)v;
    long long l = *(const long long*)p;
    if (l > 0 && l < 1048576) return (float)l;
    return *(const float*)p;
}

__global__ void k_nop() {}

// ---------------- K0: transpose conv1 weights to k-major ----------------
__global__ void k_wt(const float* __restrict__ w) {
    int o = blockIdx.x;
    for (int k = threadIdx.x; k < KDIM; k += 256) {
        int c = k & 255;
        int tap = k >> 8;
        g_wT[(size_t)k * 256 + o] = w[(size_t)o * KDIM + c * 9 + tap];
    }
}

// ---------------- K1: conv3x3, R13 structure + f32x2 FFMA2 inner product ----------------
// CTA 128pix x 64oc, grid (256,4), 8x4 microtile packed as 8x2 f32x2 pairs.
// Each lane is an independent ascending-k fma.rn -> bit-identical to R13.
__global__ void __launch_bounds__(256, 3) k_conv(const float* __restrict__ x,
                                                 const float* __restrict__ bias) {
    __shared__ __align__(16) float As[2][8][128];
    __shared__ __align__(16) float Bs[2][8][64];
    const int m0 = blockIdx.x * 128;
    const int n0 = blockIdx.y * 64;
    const int tid = threadIdx.x;
    const int lane = tid & 31, wid = tid >> 5;
    const int wm = wid & 3, wn = wid >> 2;
    const int ty2 = lane >> 3, tx2 = lane & 7;

    const int ll = tid & 127;
    const int kb = tid >> 7;
    const int m = m0 + ll;
    const int nimg = m >> 12;
    const int p = m & 4095;
    const int yy = p >> 6, xx = p & 63;
    const float* xb = x + (((size_t)nimg * CIN) << 12);
    const int brow0 = tid >> 6;
    const int bcol = tid & 63;
    const float* wb = g_wT + n0 + bcol;

    unsigned long long acc2[8][2];
#pragma unroll
    for (int i = 0; i < 8; i++) {
        acc2[i][0] = 0ull;
        acc2[i][1] = 0ull;
    }

    float va[4], vb[2];

#define LOADT(k0_)                                                              \
    {                                                                           \
        const int k0L = (k0_);                                                  \
        const int tapL = k0L >> 8;                                              \
        const int kyL = tapL / 3;                                               \
        const int kxL = tapL - kyL * 3;                                         \
        const int y2L = yy + kyL - 1, x2L = xx + kxL - 1;                       \
        const bool inbL = ((unsigned)y2L < 64u) && ((unsigned)x2L < 64u);       \
        const int aoffL = (((k0L & 255) + kb) << 12) + (y2L << 6) + x2L;        \
        _Pragma("unroll")                                                       \
        for (int tL = 0; tL < 4; tL++)                                          \
            va[tL] = inbL ? __ldg(xb + aoffL + (tL << 13)) : 0.f;               \
        _Pragma("unroll")                                                       \
        for (int tL = 0; tL < 2; tL++)                                          \
            vb[tL] = __ldg(wb + (size_t)(k0L + brow0 + 4 * tL) * 256);          \
    }

#define STORET(buf_)                                                            \
    {                                                                           \
        const int bfL = (buf_);                                                 \
        _Pragma("unroll")                                                       \
        for (int tL = 0; tL < 4; tL++)                                          \
            As[bfL][kb + 2 * tL][ll] = va[tL];                                  \
        _Pragma("unroll")                                                       \
        for (int tL = 0; tL < 2; tL++)                                          \
            Bs[bfL][brow0 + 4 * tL][bcol] = vb[tL];                             \
    }

    LOADT(0);
    STORET(0);
    __syncthreads();

    const int arow = wm * 32 + ty2 * 8;
    const int brow = wn * 32 + tx2 * 4;

    for (int s = 0; s < KSTEPS; s++) {
        const int cur = s & 1;
        if (s + 1 < KSTEPS) LOADT((s + 1) * 8);
#pragma unroll
        for (int kk = 0; kk < 8; kk++) {
            float4 a0 = *(const float4*)&As[cur][kk][arow];
            float4 a1 = *(const float4*)&As[cur][kk][arow + 4];
            float4 b0 = *(const float4*)&Bs[cur][kk][brow];
            float av[8] = {a0.x, a0.y, a0.z, a0.w, a1.x, a1.y, a1.z, a1.w};
            unsigned long long b2lo = pk2(b0.x, b0.y);
            unsigned long long b2hi = pk2(b0.z, b0.w);
#pragma unroll
            for (int i2 = 0; i2 < 8; i2++) {
                unsigned long long a2 = pk2(av[i2], av[i2]);
                fma2(acc2[i2][0], a2, b2lo);
                fma2(acc2[i2][1], a2, b2hi);
            }
        }
        if (s + 1 < KSTEPS) STORET((s + 1) & 1);
        __syncthreads();
    }
#undef LOADT
#undef STORET

    // epilogue: unpack + bias + relu -> g_h NCHW
#pragma unroll
    for (int i = 0; i < 8; i++) {
        int mo = m0 + arow + i;
        int n = mo >> 12;
        int pp = mo & 4095;
#pragma unroll
        for (int j2 = 0; j2 < 2; j2++) {
            float lo, hi;
            upk2(lo, hi, acc2[i][j2]);
            int o = n0 + brow + j2 * 2;
            g_h[(((size_t)n * CIN + o) << 12) + pp] = fmaxf(lo + bias[o], 0.f);
            g_h[(((size_t)n * CIN + o + 1) << 12) + pp] = fmaxf(hi + bias[o + 1], 0.f);
        }
    }
}

// ---------------- K2: heads v2 (unchanged from R14) ----------------
__global__ void __launch_bounds__(256) k_heads(const float* __restrict__ lw,
                                               const float* __restrict__ lb,
                                               const float* __restrict__ sw,
                                               const float* __restrict__ sb,
                                               float* __restrict__ out,
                                               const void* pih, const void* piw) {
    extern __shared__ float sm[];
    float* ws = sm + WS_OFF;
    float* hs = sm + HS_OFF;
    float* so = sm + SO_OFF;
    const int tid = threadIdx.x;
    const int p0 = blockIdx.x * 32;
    const int n = p0 >> 12;
    const int pbase = p0 & 4095;

    for (int idx = tid; idx < 54 * 256; idx += 256) {
        int ch = idx >> 8, k = idx & 255;
        float v = (ch < 36) ? lw[ch * 256 + k] : sw[(ch - 36) * 256 + k];
        ws[ch * 257 + k] = v;
    }
    for (int idx = tid; idx < 32 * 256; idx += 256) {
        int c = idx >> 5, px = idx & 31;
        hs[px * 257 + c] = g_h[(((size_t)n * CIN + c) << 12) + pbase + px];
    }
    __syncthreads();

    for (int round = 0; round < 2; round++) {
        int task = tid + round * 256;
        int ch = task & 63;
        int pg = task >> 6;
        if (ch < 54) {
            const float* wr = ws + ch * 257;
            const float* h0 = hs + (pg * 4 + 0) * 257;
            const float* h1 = hs + (pg * 4 + 1) * 257;
            const float* h2 = hs + (pg * 4 + 2) * 257;
            const float* h3 = hs + (pg * 4 + 3) * 257;
            float a0 = 0.f, a1 = 0.f, a2 = 0.f, a3 = 0.f;
#pragma unroll 4
            for (int k = 0; k < 256; k++) {
                float w = wr[k];
                a0 += w * h0[k];
                a1 += w * h1[k];
                a2 += w * h2[k];
                a3 += w * h3[k];
            }
            float bv = (ch < 36) ? lb[ch] : sb[ch - 36];
            float r[4] = {a0 + bv, a1 + bv, a2 + bv, a3 + bv};
#pragma unroll
            for (int j = 0; j < 4; j++) {
                int px = pg * 4 + j;
                int pp = pbase + px;
                so[px * 56 + ch] = r[j];
                if (ch < 36)
                    out[OFF_LOC + (size_t)n * 147456 + (size_t)pp * 36 + ch] = r[j];
                else
                    out[OFF_SCORE + (size_t)n * 73728 + (size_t)pp * 18 + (ch - 36)] = r[j];
            }
        }
    }
    __syncthreads();

    const float imh = read_dim(pih), imw = read_dim(piw);
    for (int t = tid; t < 288; t += 256) {
        int px = t / 9;
        int a = t - px * 9;
        int pp = pbase + px;
        int y = pp >> 6, xq = pp & 63;
        const double RAT[3] = {0.5, 1.0, 2.0};
        const double SCL[3] = {8.0, 16.0, 32.0};
        int ri = a / 3, sj = a % 3;
        double hh = 7.0 * SCL[sj] * sqrt(RAT[ri]);
        double wd = 7.0 * SCL[sj] * sqrt(1.0 / RAT[ri]);
        float ab0 = (float)(3.5 - hh / 2.0), ab1 = (float)(3.5 - wd / 2.0);
        float ab2 = (float)(3.5 + hh / 2.0), ab3 = (float)(3.5 + wd / 2.0);
        float shy = (float)(y * 16), shx = (float)(xq * 16);
        float A0 = shy + ab0, A1 = shx + ab1, A2 = shy + ab2, A3 = shx + ab3;
        long aidx = (long)pp * NA + a;
        if (n == 0) {
            float* ao = out + OFF_ANCH + (size_t)aidx * 4;
            ao[0] = A0; ao[1] = A1; ao[2] = A2; ao[3] = A3;
        }
        float ah = A2 - A0, aw = A3 - A1;
        float acy = A0 + 0.5f * ah, acx = A1 + 0.5f * aw;
        const float* sop = so + px * 56;
        float dy = sop[a * 4 + 0], dx = sop[a * 4 + 1];
        float dh = sop[a * 4 + 2], dw = sop[a * 4 + 3];
        float cy = dy * ah + acy;
        float cx = dx * aw + acx;
        float bh = expf(dh) * ah;
        float bw = expf(dw) * aw;
        float y1 = fminf(fmaxf(cy - 0.5f * bh, 0.f), imh);
        float x1 = fminf(fmaxf(cx - 0.5f * bw, 0.f), imw);
        float y2 = fminf(fmaxf(cy + 0.5f * bh, 0.f), imh);
        float x2 = fminf(fmaxf(cx + 0.5f * bw, 0.f), imw);
        bool valid = ((y2 - y1) >= 16.f) && ((x2 - x1) >= 16.f);
        float s0 = sop[36 + 2 * a], s1 = sop[37 + 2 * a];
        float mm = fmaxf(s0, s1);
        float e0 = expf(s0 - mm), e1 = expf(s1 - mm);
        float fg = __fdiv_rn(e1, __fadd_rn(e0, e1));
        float sc = valid ? fg : -INFINITY;
        unsigned u = __float_as_uint(sc);
        unsigned sbits = (u & 0x80000000u) ? ~u : (u | 0x80000000u);
        size_t gi = (size_t)n * APIMG + aidx;
        g_key[gi] = ~sbits;
        float* bp = g_boxes + gi * 4;
        bp[0] = y1; bp[1] = x1; bp[2] = y2; bp[3] = x2;
    }
}

// ---------------- K3: exact top-6000 (radix select + bitonic sort) ----------------
__global__ void __launch_bounds__(1024) k_topk() {
    extern __shared__ unsigned smem[];
    unsigned* keys = smem;
    unsigned long long* buf = (unsigned long long*)(smem + APIMG);
    __shared__ int hist[256];
    __shared__ unsigned s_val;
    __shared__ int s_rem;
    __shared__ int s_cnt;
    int n = blockIdx.x;
    int tid = threadIdx.x;
    const unsigned* gk = g_key + (size_t)n * APIMG;
    for (int i = tid; i < APIMG; i += 1024) keys[i] = gk[i];
    __syncthreads();

    unsigned prefix = 0, mask = 0;
    int rem = NPRE;
    for (int pass = 0; pass < 4; pass++) {
        int shift = 24 - pass * 8;
        if (tid < 256) hist[tid] = 0;
        __syncthreads();
        for (int i = tid; i < APIMG; i += 1024) {
            unsigned k = keys[i];
            if ((k & mask) == prefix) atomicAdd(&hist[(k >> shift) & 255], 1);
        }
        __syncthreads();
        if (tid == 0) {
            int accu = 0;
            for (int d = 0; d < 256; d++) {
                int c = hist[d];
                if (accu + c >= rem) { s_val = prefix | ((unsigned)d << shift); s_rem = rem - accu; break; }
                accu += c;
            }
        }
        __syncthreads();
        prefix = s_val;
        rem = s_rem;
        mask |= (0xFFu << shift);
    }
    unsigned T = prefix;
    int r = rem;

    unsigned ipref = 0, im = 0;
    int ir = r;
    for (int pass = 0; pass < 2; pass++) {
        int shift = 8 - pass * 8;
        if (tid < 256) hist[tid] = 0;
        __syncthreads();
        for (int i = tid; i < APIMG; i += 1024) {
            if (keys[i] == T && (((unsigned)i & im) == ipref))
                atomicAdd(&hist[((unsigned)i >> shift) & 255], 1);
        }
        __syncthreads();
        if (tid == 0) {
            int accu = 0;
            for (int d = 0; d < 256; d++) {
                int c = hist[d];
                if (accu + c >= ir) { s_val = ipref | ((unsigned)d << shift); s_rem = ir - accu; break; }
                accu += c;
            }
        }
        __syncthreads();
        ipref = s_val;
        ir = s_rem;
        im |= (0xFFu << shift);
    }
    unsigned idxT = ipref;

    if (tid == 0) s_cnt = 0;
    __syncthreads();
    for (int i = tid; i < APIMG; i += 1024) {
        unsigned k = keys[i];
        if (k < T || (k == T && (unsigned)i <= idxT)) {
            int pos = atomicAdd(&s_cnt, 1);
            buf[pos] = (((unsigned long long)k) << 32) | (unsigned)i;
        }
    }
    __syncthreads();
    int cnt = s_cnt;
    for (int i = tid; i < 8192; i += 1024)
        if (i >= cnt) buf[i] = 0xFFFFFFFFFFFFFFFFull;
    __syncthreads();
    for (int size = 2; size <= 8192; size <<= 1) {
        for (int stride = size >> 1; stride > 0; stride >>= 1) {
            for (int i = tid; i < 8192; i += 1024) {
                int ixj = i ^ stride;
                if (ixj > i) {
                    bool up = ((i & size) == 0);
                    unsigned long long vaa = buf[i], vbb = buf[ixj];
                    if ((vaa > vbb) == up) { buf[i] = vbb; buf[ixj] = vaa; }
                }
            }
            __syncthreads();
        }
    }
    for (int r2 = tid; r2 < NPRE; r2 += 1024) {
        unsigned idx = (unsigned)(buf[r2] & 0xFFFFFFFFull);
        float4 bb = *(const float4*)(g_boxes + ((size_t)n * APIMG + idx) * 4);
        *(float4*)(g_top + ((size_t)n * NPRE + r2) * 4) = bb;
    }
}

// ---------------- K4: NMS bitmask (upper triangle) ----------------
__global__ void __launch_bounds__(64) k_mask() {
    int n = blockIdx.z;
    int it = blockIdx.x, jt = blockIdx.y;
    if (jt < it) return;
    __shared__ float4 sb[64];
    __shared__ float sarea[64];
    int tid = threadIdx.x;
    int j = jt * 64 + tid;
    float4 bj = (j < NPRE) ? *(const float4*)(g_top + ((size_t)n * NPRE + j) * 4)
                           : make_float4(0, 0, 0, 0);
    sb[tid] = bj;
    sarea[tid] = (bj.z - bj.x) * (bj.w - bj.y);
    __syncthreads();
    int i = it * 64 + tid;
    if (i >= NPRE) return;
    float4 bi = *(const float4*)(g_top + ((size_t)n * NPRE + i) * 4);
    float ai = (bi.z - bi.x) * (bi.w - bi.y);
    unsigned long long bits = 0;
    int jmax = min(64, NPRE - jt * 64);
#pragma unroll 4
    for (int q = 0; q < 64; q++) {
        if (q < jmax) {
            float4 b2 = sb[q];
            float ty0 = fmaxf(bi.x, b2.x), tx0 = fmaxf(bi.y, b2.y);
            float by0 = fminf(bi.z, b2.z), bx0 = fminf(bi.w, b2.w);
            float ih = fmaxf(by0 - ty0, 0.f), iw = fmaxf(bx0 - tx0, 0.f);
            float inter = ih * iw;
            float iou = inter / (ai + sarea[q] - inter + 1e-9f);
            if (iou > 0.7f) bits |= (1ull << q);
        }
    }
    g_mask[((size_t)n * NPRE + i) * NWORDS + jt] = bits;
}

// ---------------- K5: sequential suppression + ROI writeout ----------------
__global__ void __launch_bounds__(32) k_nms(float* __restrict__ out) {
    int n = blockIdx.x;
    int lane = threadIdx.x;
    __shared__ int s_keep[NPOST];
    __shared__ int s_cnt;
    unsigned long long remv0 = 0, remv1 = 0, remv2 = 0;
    int cnt = 0;
    const unsigned long long* mbase = g_mask + (size_t)n * NPRE * NWORDS;
    for (int w = 0; w < NWORDS && cnt < NPOST; w++) {
        int owner = w & 31, slot = w >> 5;
        unsigned long long myv = (slot == 0) ? remv0 : ((slot == 1) ? remv1 : remv2);
        unsigned long long cur = __shfl_sync(0xffffffffu, myv, owner);
        int bmax = min(64, NPRE - (w << 6));
        for (int b = 0; b < bmax; b++) {
            if (!((cur >> b) & 1ull)) {
                int i = (w << 6) + b;
                if (lane == 0) s_keep[cnt] = i;
                cnt++;
                const unsigned long long* row = mbase + (size_t)i * NWORDS;
                if (lane >= w && lane < NWORDS) remv0 |= __ldg(row + lane);
                if (lane + 32 >= w && lane + 32 < NWORDS) remv1 |= __ldg(row + lane + 32);
                if (lane + 64 >= w && lane + 64 < NWORDS) remv2 |= __ldg(row + lane + 64);
                if (cnt >= NPOST) break;
                myv = (slot == 0) ? remv0 : ((slot == 1) ? remv1 : remv2);
                cur |= __shfl_sync(0xffffffffu, myv, owner);
            }
        }
    }
    if (lane == 0) s_cnt = cnt;
    __syncwarp();
    if (lane == 0 && cnt < NPOST) {
        int ptr = 0, fill = cnt;
        for (int i = 0; i < NPRE && fill < NPOST; i++) {
            if (ptr < cnt && s_keep[ptr] == i) ptr++;
            else s_keep[fill++] = i;
        }
    }
    __syncwarp();
    for (int r2 = lane; r2 < NPOST; r2 += 32) {
        int idx = s_keep[r2];
        float4 bb = *(const float4*)(g_top + ((size_t)n * NPRE + idx) * 4);
        float* o = out + OFF_ROIS + ((size_t)n * NPOST + r2) * 4;
        o[0] = bb.x; o[1] = bb.y; o[2] = bb.z; o[3] = bb.w;
        out[OFF_RIDX + n * NPOST + r2] = (float)n;
    }
}

// ---------------- launch ----------------
extern "C" void kernel_launch(void* const* d_in, const int* in_sizes, int n_in,
                              void* d_out, int out_size) {
    const float* x  = (const float*)d_in[0];
    const float* w1 = (const float*)d_in[1];
    const float* b1 = (const float*)d_in[2];
    const float* sw = (const float*)d_in[3];
    const float* sb = (const float*)d_in[4];
    const float* lw = (const float*)d_in[5];
    const float* lb = (const float*)d_in[6];
    const void* pih = d_in[7];
    const void* piw = d_in[8];
    float* out = (float*)d_out;

    k_wt<<<256, 256>>>(w1);                 // launch 1
    k_nop<<<1, 32>>>();                     // launch 2
    k_nop<<<1, 32>>>();                     // launch 3
    k_conv<<<dim3(256, 4), 256>>>(x, b1);   // launch 4 -> ncu captures THIS
    cudaFuncSetAttribute(k_heads, cudaFuncAttributeMaxDynamicSharedMemorySize, HEADS_SMEM_B);
    k_heads<<<1024, 256, HEADS_SMEM_B>>>(lw, lb, sw, sb, out, pih, piw);
    cudaFuncSetAttribute(k_topk, cudaFuncAttributeMaxDynamicSharedMemorySize, 213504);
    k_topk<<<8, 1024, 212992>>>();
    k_mask<<<dim3(94, 94, 8), 64>>>();
    k_nms<<<8, 32>>>(out);
}

// round 16
// speedup vs baseline: 2.1440x; 1.0160x over previous
#include <cuda_runtime.h>
#include <math.h>
#include <stdint.h>

#define NIMG 8
#define CIN 256
#define HW 4096
#define NA 9
#define APIMG 36864
#define NPRE 6000
#define NPOST 300
#define KDIM 2304
#define NWORDS 94
#define KSTEPS 288

#define OFF_LOC   0
#define OFF_SCORE 1179648
#define OFF_ROIS  1769472
#define OFF_RIDX  1779072
#define OFF_ANCH  1781472

// k_heads smem layout (floats): ws[54][257] | hs[256][36] | so[32][56]
#define WS_OFF 0
#define HS_OFF 13880
#define SO_OFF 23096
#define HEADS_SMEM_F 24888
#define HEADS_SMEM_B (HEADS_SMEM_F * 4)   // 99552

// ---------------- static device scratch ----------------
__device__ float g_wT[KDIM * 256];
__device__ float g_h[NIMG * CIN * HW];
__device__ float g_boxes[NIMG * APIMG * 4];
__device__ unsigned g_key[NIMG * APIMG];
__device__ float g_top[NIMG * NPRE * 4];
__device__ unsigned long long g_mask[(size_t)NIMG * NPRE * NWORDS];

__device__ __forceinline__ unsigned long long pk2(float lo, float hi) {
    unsigned long long r;
    asm("mov.b64 %0, {%1, %2};" : "=l"(r) : "f"(lo), "f"(hi));
    return r;
}
__device__ __forceinline__ void fma2(unsigned long long& c, unsigned long long a,
                                     unsigned long long b) {
    asm("fma.rn.f32x2 %0, %1, %2, %0;" : "+l"(c) : "l"(a), "l"(b));
}
__device__ __forceinline__ void upk2(float& lo, float& hi, unsigned long long v) {
    asm("mov.b64 {%0, %1}, %2;" : "=f"(lo), "=f"(hi) : "l"(v));
}
__device__ __forceinline__ float read_dim(const void* p) {
    int v = *(const int*)p;
    if (v > 0 && v < 1048576) return (float)v;
    long long l = *(const long long*)p;
    if (l > 0 && l < 1048576) return (float)l;
    return *(const float*)p;
}

// ---------------- K0: transpose conv1 weights to k-major ----------------
__global__ void k_wt(const float* __restrict__ w) {
    int o = blockIdx.x;
    for (int k = threadIdx.x; k < KDIM; k += 256) {
        int c = k & 255;
        int tap = k >> 8;
        g_wT[(size_t)k * 256 + o] = w[(size_t)o * KDIM + c * 9 + tap];
    }
}

// ---------------- K1: conv (unchanged from R15 best) ----------------
__global__ void __launch_bounds__(256, 3) k_conv(const float* __restrict__ x,
                                                 const float* __restrict__ bias) {
    __shared__ __align__(16) float As[2][8][128];
    __shared__ __align__(16) float Bs[2][8][64];
    const int m0 = blockIdx.x * 128;
    const int n0 = blockIdx.y * 64;
    const int tid = threadIdx.x;
    const int lane = tid & 31, wid = tid >> 5;
    const int wm = wid & 3, wn = wid >> 2;
    const int ty2 = lane >> 3, tx2 = lane & 7;

    const int ll = tid & 127;
    const int kb = tid >> 7;
    const int m = m0 + ll;
    const int nimg = m >> 12;
    const int p = m & 4095;
    const int yy = p >> 6, xx = p & 63;
    const float* xb = x + (((size_t)nimg * CIN) << 12);
    const int brow0 = tid >> 6;
    const int bcol = tid & 63;
    const float* wb = g_wT + n0 + bcol;

    unsigned long long acc2[8][2];
#pragma unroll
    for (int i = 0; i < 8; i++) {
        acc2[i][0] = 0ull;
        acc2[i][1] = 0ull;
    }

    float va[4], vb[2];

#define LOADT(k0_)                                                              \
    {                                                                           \
        const int k0L = (k0_);                                                  \
        const int tapL = k0L >> 8;                                              \
        const int kyL = tapL / 3;                                               \
        const int kxL = tapL - kyL * 3;                                         \
        const int y2L = yy + kyL - 1, x2L = xx + kxL - 1;                       \
        const bool inbL = ((unsigned)y2L < 64u) && ((unsigned)x2L < 64u);       \
        const int aoffL = (((k0L & 255) + kb) << 12) + (y2L << 6) + x2L;        \
        _Pragma("unroll")                                                       \
        for (int tL = 0; tL < 4; tL++)                                          \
            va[tL] = inbL ? __ldg(xb + aoffL + (tL << 13)) : 0.f;               \
        _Pragma("unroll")                                                       \
        for (int tL = 0; tL < 2; tL++)                                          \
            vb[tL] = __ldg(wb + (size_t)(k0L + brow0 + 4 * tL) * 256);          \
    }

#define STORET(buf_)                                                            \
    {                                                                           \
        const int bfL = (buf_);                                                 \
        _Pragma("unroll")                                                       \
        for (int tL = 0; tL < 4; tL++)                                          \
            As[bfL][kb + 2 * tL][ll] = va[tL];                                  \
        _Pragma("unroll")                                                       \
        for (int tL = 0; tL < 2; tL++)                                          \
            Bs[bfL][brow0 + 4 * tL][bcol] = vb[tL];                             \
    }

    LOADT(0);
    STORET(0);
    __syncthreads();

    const int arow = wm * 32 + ty2 * 8;
    const int brow = wn * 32 + tx2 * 4;

    for (int s = 0; s < KSTEPS; s++) {
        const int cur = s & 1;
        if (s + 1 < KSTEPS) LOADT((s + 1) * 8);
#pragma unroll
        for (int kk = 0; kk < 8; kk++) {
            float4 a0 = *(const float4*)&As[cur][kk][arow];
            float4 a1 = *(const float4*)&As[cur][kk][arow + 4];
            float4 b0 = *(const float4*)&Bs[cur][kk][brow];
            float av[8] = {a0.x, a0.y, a0.z, a0.w, a1.x, a1.y, a1.z, a1.w};
            unsigned long long b2lo = pk2(b0.x, b0.y);
            unsigned long long b2hi = pk2(b0.z, b0.w);
#pragma unroll
            for (int i2 = 0; i2 < 8; i2++) {
                unsigned long long a2 = pk2(av[i2], av[i2]);
                fma2(acc2[i2][0], a2, b2lo);
                fma2(acc2[i2][1], a2, b2hi);
            }
        }
        if (s + 1 < KSTEPS) STORET((s + 1) & 1);
        __syncthreads();
    }
#undef LOADT
#undef STORET

#pragma unroll
    for (int i = 0; i < 8; i++) {
        int mo = m0 + arow + i;
        int n = mo >> 12;
        int pp = mo & 4095;
#pragma unroll
        for (int j2 = 0; j2 < 2; j2++) {
            float lo, hi;
            upk2(lo, hi, acc2[i][j2]);
            int o = n0 + brow + j2 * 2;
            g_h[(((size_t)n * CIN + o) << 12) + pp] = fmaxf(lo + bias[o], 0.f);
            g_h[(((size_t)n * CIN + o + 1) << 12) + pp] = fmaxf(hi + bias[o + 1], 0.f);
        }
    }
}

// ---------------- K2: heads v3 — k-major h tile, float4 pixel-group loads ----------------
__global__ void __launch_bounds__(256) k_heads(const float* __restrict__ lw,
                                               const float* __restrict__ lb,
                                               const float* __restrict__ sw,
                                               const float* __restrict__ sb,
                                               float* __restrict__ out,
                                               const void* pih, const void* piw) {
    extern __shared__ float sm[];
    float* ws = sm + WS_OFF;   // [54][257]
    float* hs = sm + HS_OFF;   // [256][36] k-major
    float* so = sm + SO_OFF;   // [32][56]
    const int tid = threadIdx.x;
    const int p0 = blockIdx.x * 32;
    const int n = p0 >> 12;
    const int pbase = p0 & 4095;

    for (int idx = tid; idx < 54 * 256; idx += 256) {
        int ch = idx >> 8, k = idx & 255;
        float v = (ch < 36) ? lw[ch * 256 + k] : sw[(ch - 36) * 256 + k];
        ws[ch * 257 + k] = v;
    }
    for (int idx = tid; idx < 32 * 256; idx += 256) {
        int c = idx >> 5, px = idx & 31;
        hs[c * 36 + px] = g_h[(((size_t)n * CIN + c) << 12) + pbase + px];
    }
    __syncthreads();

    for (int round = 0; round < 2; round++) {
        int task = tid + round * 256;
        int ch = task & 63;
        int pg = task >> 6;
        if (ch < 54) {
            const float* wr = ws + ch * 257;
            const float* hp = hs + pg * 4;
            float a0 = 0.f, a1 = 0.f, a2 = 0.f, a3 = 0.f;
#pragma unroll 4
            for (int k = 0; k < 256; k++) {
                float w = wr[k];
                float4 h = *(const float4*)(hp + k * 36);
                a0 += w * h.x;
                a1 += w * h.y;
                a2 += w * h.z;
                a3 += w * h.w;
            }
            float bv = (ch < 36) ? lb[ch] : sb[ch - 36];
            float r[4] = {a0 + bv, a1 + bv, a2 + bv, a3 + bv};
#pragma unroll
            for (int j = 0; j < 4; j++) {
                int px = pg * 4 + j;
                int pp = pbase + px;
                so[px * 56 + ch] = r[j];
                if (ch < 36)
                    out[OFF_LOC + (size_t)n * 147456 + (size_t)pp * 36 + ch] = r[j];
                else
                    out[OFF_SCORE + (size_t)n * 73728 + (size_t)pp * 18 + (ch - 36)] = r[j];
            }
        }
    }
    __syncthreads();

    const float imh = read_dim(pih), imw = read_dim(piw);
    for (int t = tid; t < 288; t += 256) {
        int px = t / 9;
        int a = t - px * 9;
        int pp = pbase + px;
        int y = pp >> 6, xq = pp & 63;
        const double RAT[3] = {0.5, 1.0, 2.0};
        const double SCL[3] = {8.0, 16.0, 32.0};
        int ri = a / 3, sj = a % 3;
        double hh = 7.0 * SCL[sj] * sqrt(RAT[ri]);
        double wd = 7.0 * SCL[sj] * sqrt(1.0 / RAT[ri]);
        float ab0 = (float)(3.5 - hh / 2.0), ab1 = (float)(3.5 - wd / 2.0);
        float ab2 = (float)(3.5 + hh / 2.0), ab3 = (float)(3.5 + wd / 2.0);
        float shy = (float)(y * 16), shx = (float)(xq * 16);
        float A0 = shy + ab0, A1 = shx + ab1, A2 = shy + ab2, A3 = shx + ab3;
        long aidx = (long)pp * NA + a;
        if (n == 0) {
            float* ao = out + OFF_ANCH + (size_t)aidx * 4;
            ao[0] = A0; ao[1] = A1; ao[2] = A2; ao[3] = A3;
        }
        float ah = A2 - A0, aw = A3 - A1;
        float acy = A0 + 0.5f * ah, acx = A1 + 0.5f * aw;
        const float* sop = so + px * 56;
        float dy = sop[a * 4 + 0], dx = sop[a * 4 + 1];
        float dh = sop[a * 4 + 2], dw = sop[a * 4 + 3];
        float cy = dy * ah + acy;
        float cx = dx * aw + acx;
        float bh = expf(dh) * ah;
        float bw = expf(dw) * aw;
        float y1 = fminf(fmaxf(cy - 0.5f * bh, 0.f), imh);
        float x1 = fminf(fmaxf(cx - 0.5f * bw, 0.f), imw);
        float y2 = fminf(fmaxf(cy + 0.5f * bh, 0.f), imh);
        float x2 = fminf(fmaxf(cx + 0.5f * bw, 0.f), imw);
        bool valid = ((y2 - y1) >= 16.f) && ((x2 - x1) >= 16.f);
        float s0 = sop[36 + 2 * a], s1 = sop[37 + 2 * a];
        float mm = fmaxf(s0, s1);
        float e0 = expf(s0 - mm), e1 = expf(s1 - mm);
        float fg = __fdiv_rn(e1, __fadd_rn(e0, e1));
        float sc = valid ? fg : -INFINITY;
        unsigned u = __float_as_uint(sc);
        unsigned sbits = (u & 0x80000000u) ? ~u : (u | 0x80000000u);
        size_t gi = (size_t)n * APIMG + aidx;
        g_key[gi] = ~sbits;
        float* bp = g_boxes + gi * 4;
        bp[0] = y1; bp[1] = x1; bp[2] = y2; bp[3] = x2;
    }
}

// ---------------- K3: exact top-6000 (radix select w/ parallel scan + bitonic) ----------------
__global__ void __launch_bounds__(1024) k_topk() {
    extern __shared__ unsigned smem[];
    unsigned* keys = smem;
    unsigned long long* buf = (unsigned long long*)(smem + APIMG);
    __shared__ int hist[256];
    __shared__ int s_wsum[8];
    __shared__ unsigned s_val;
    __shared__ int s_rem;
    __shared__ int s_cnt;
    int n = blockIdx.x;
    int tid = threadIdx.x;
    const int lane = tid & 31, warp = tid >> 5;
    const unsigned* gk = g_key + (size_t)n * APIMG;
    for (int i = tid; i < APIMG; i += 1024) keys[i] = gk[i];
    __syncthreads();

// parallel select of bucket containing rank `rem_`; digit = tid (0..255)
#define SEL_SCAN(prefix_, shift_, rem_)                                         \
    {                                                                           \
        int vS = 0, incS = 0;                                                   \
        if (tid < 256) {                                                        \
            vS = hist[tid];                                                     \
            incS = vS;                                                          \
            _Pragma("unroll")                                                   \
            for (int oS = 1; oS < 32; oS <<= 1) {                               \
                int tS = __shfl_up_sync(0xffffffffu, incS, oS);                 \
                if (lane >= oS) incS += tS;                                     \
            }                                                                   \
            if (lane == 31) s_wsum[warp] = incS;                                \
        }                                                                       \
        __syncthreads();                                                        \
        if (tid < 8) {                                                          \
            int wv = s_wsum[tid];                                               \
            _Pragma("unroll")                                                   \
            for (int oS = 1; oS < 8; oS <<= 1) {                                \
                int tS = __shfl_up_sync(0xffu, wv, oS);                         \
                if (tid >= oS) wv += tS;                                        \
            }                                                                   \
            s_wsum[tid] = wv;                                                   \
        }                                                                       \
        __syncthreads();                                                        \
        if (tid < 256) {                                                        \
            int off = (warp > 0) ? s_wsum[warp - 1] : 0;                        \
            int incl = incS + off;                                              \
            int excl = incl - vS;                                               \
            if (excl < (rem_) && (rem_) <= incl) {                              \
                s_val = (prefix_) | ((unsigned)tid << (shift_));                \
                s_rem = (rem_) - excl;                                          \
            }                                                                   \
        }                                                                       \
        __syncthreads();                                                        \
    }

    unsigned prefix = 0, mask = 0;
    int rem = NPRE;
    for (int pass = 0; pass < 4; pass++) {
        int shift = 24 - pass * 8;
        if (tid < 256) hist[tid] = 0;
        __syncthreads();
        for (int i = tid; i < APIMG; i += 1024) {
            unsigned k = keys[i];
            if ((k & mask) == prefix) atomicAdd(&hist[(k >> shift) & 255], 1);
        }
        __syncthreads();
        SEL_SCAN(prefix, shift, rem);
        prefix = s_val;
        rem = s_rem;
        mask |= (0xFFu << shift);
    }
    unsigned T = prefix;
    int r = rem;

    unsigned ipref = 0, im = 0;
    int ir = r;
    for (int pass = 0; pass < 2; pass++) {
        int shift = 8 - pass * 8;
        if (tid < 256) hist[tid] = 0;
        __syncthreads();
        for (int i = tid; i < APIMG; i += 1024) {
            if (keys[i] == T && (((unsigned)i & im) == ipref))
                atomicAdd(&hist[((unsigned)i >> shift) & 255], 1);
        }
        __syncthreads();
        SEL_SCAN(ipref, shift, ir);
        ipref = s_val;
        ir = s_rem;
        im |= (0xFFu << shift);
    }
    unsigned idxT = ipref;
#undef SEL_SCAN

    if (tid == 0) s_cnt = 0;
    __syncthreads();
    for (int i = tid; i < APIMG; i += 1024) {
        unsigned k = keys[i];
        if (k < T || (k == T && (unsigned)i <= idxT)) {
            int pos = atomicAdd(&s_cnt, 1);
            buf[pos] = (((unsigned long long)k) << 32) | (unsigned)i;
        }
    }
    __syncthreads();
    int cnt = s_cnt;
    for (int i = tid; i < 8192; i += 1024)
        if (i >= cnt) buf[i] = 0xFFFFFFFFFFFFFFFFull;
    __syncthreads();
    for (int size = 2; size <= 8192; size <<= 1) {
        for (int stride = size >> 1; stride > 0; stride >>= 1) {
            for (int i = tid; i < 8192; i += 1024) {
                int ixj = i ^ stride;
                if (ixj > i) {
                    bool up = ((i & size) == 0);
                    unsigned long long vaa = buf[i], vbb = buf[ixj];
                    if ((vaa > vbb) == up) { buf[i] = vbb; buf[ixj] = vaa; }
                }
            }
            __syncthreads();
        }
    }
    for (int r2 = tid; r2 < NPRE; r2 += 1024) {
        unsigned idx = (unsigned)(buf[r2] & 0xFFFFFFFFull);
        float4 bb = *(const float4*)(g_boxes + ((size_t)n * APIMG + idx) * 4);
        *(float4*)(g_top + ((size_t)n * NPRE + r2) * 4) = bb;
    }
}

// ---------------- K4: NMS bitmask — 256-thread blocks, 4 i-tiles per j-tile ----------------
__global__ void __launch_bounds__(256) k_mask() {
    int n = blockIdx.z;
    int jt = blockIdx.x;
    int it0 = blockIdx.y * 256;
    if (jt < (it0 >> 6)) return;   // entire block in lower triangle
    __shared__ float4 sb[64];
    __shared__ float sarea[64];
    int tid = threadIdx.x;
    if (tid < 64) {
        int j = jt * 64 + tid;
        float4 bj = (j < NPRE) ? *(const float4*)(g_top + ((size_t)n * NPRE + j) * 4)
                               : make_float4(0, 0, 0, 0);
        sb[tid] = bj;
        sarea[tid] = (bj.z - bj.x) * (bj.w - bj.y);
    }
    __syncthreads();
    int i = it0 + tid;
    if (i >= NPRE) return;
    if (jt < (i >> 6)) return;     // never consumed
    float4 bi = *(const float4*)(g_top + ((size_t)n * NPRE + i) * 4);
    float ai = (bi.z - bi.x) * (bi.w - bi.y);
    unsigned long long bits = 0;
    int jmax = min(64, NPRE - jt * 64);
#pragma unroll 4
    for (int q = 0; q < 64; q++) {
        if (q < jmax) {
            float4 b2 = sb[q];
            float ty0 = fmaxf(bi.x, b2.x), tx0 = fmaxf(bi.y, b2.y);
            float by0 = fminf(bi.z, b2.z), bx0 = fminf(bi.w, b2.w);
            float ih = fmaxf(by0 - ty0, 0.f), iw = fmaxf(bx0 - tx0, 0.f);
            float inter = ih * iw;
            float iou = inter / (ai + sarea[q] - inter + 1e-9f);
            if (iou > 0.7f) bits |= (1ull << q);
        }
    }
    g_mask[((size_t)n * NPRE + i) * NWORDS + jt] = bits;
}

// ---------------- K5: sequential suppression + ROI writeout ----------------
__global__ void __launch_bounds__(32) k_nms(float* __restrict__ out) {
    int n = blockIdx.x;
    int lane = threadIdx.x;
    __shared__ int s_keep[NPOST];
    __shared__ int s_cnt;
    unsigned long long remv0 = 0, remv1 = 0, remv2 = 0;
    int cnt = 0;
    const unsigned long long* mbase = g_mask + (size_t)n * NPRE * NWORDS;
    for (int w = 0; w < NWORDS && cnt < NPOST; w++) {
        int owner = w & 31, slot = w >> 5;
        unsigned long long myv = (slot == 0) ? remv0 : ((slot == 1) ? remv1 : remv2);
        unsigned long long cur = __shfl_sync(0xffffffffu, myv, owner);
        int bmax = min(64, NPRE - (w << 6));
        for (int b = 0; b < bmax; b++) {
            if (!((cur >> b) & 1ull)) {
                int i = (w << 6) + b;
                if (lane == 0) s_keep[cnt] = i;
                cnt++;
                const unsigned long long* row = mbase + (size_t)i * NWORDS;
                if (lane >= w && lane < NWORDS) remv0 |= __ldg(row + lane);
                if (lane + 32 >= w && lane + 32 < NWORDS) remv1 |= __ldg(row + lane + 32);
                if (lane + 64 >= w && lane + 64 < NWORDS) remv2 |= __ldg(row + lane + 64);
                if (cnt >= NPOST) break;
                myv = (slot == 0) ? remv0 : ((slot == 1) ? remv1 : remv2);
                cur |= __shfl_sync(0xffffffffu, myv, owner);
            }
        }
    }
    if (lane == 0) s_cnt = cnt;
    __syncwarp();
    if (lane == 0 && cnt < NPOST) {
        int ptr = 0, fill = cnt;
        for (int i = 0; i < NPRE && fill < NPOST; i++) {
            if (ptr < cnt && s_keep[ptr] == i) ptr++;
            else s_keep[fill++] = i;
        }
    }
    __syncwarp();
    for (int r2 = lane; r2 < NPOST; r2 += 32) {
        int idx = s_keep[r2];
        float4 bb = *(const float4*)(g_top + ((size_t)n * NPRE + idx) * 4);
        float* o = out + OFF_ROIS + ((size_t)n * NPOST + r2) * 4;
        o[0] = bb.x; o[1] = bb.y; o[2] = bb.z; o[3] = bb.w;
        out[OFF_RIDX + n * NPOST + r2] = (float)n;
    }
}

// ---------------- launch ----------------
extern "C" void kernel_launch(void* const* d_in, const int* in_sizes, int n_in,
                              void* d_out, int out_size) {
    const float* x  = (const float*)d_in[0];
    const float* w1 = (const float*)d_in[1];
    const float* b1 = (const float*)d_in[2];
    const float* sw = (const float*)d_in[3];
    const float* sb = (const float*)d_in[4];
    const float* lw = (const float*)d_in[5];
    const float* lb = (const float*)d_in[6];
    const void* pih = d_in[7];
    const void* piw = d_in[8];
    float* out = (float*)d_out;

    k_wt<<<256, 256>>>(w1);
    k_conv<<<dim3(256, 4), 256>>>(x, b1);
    cudaFuncSetAttribute(k_heads, cudaFuncAttributeMaxDynamicSharedMemorySize, HEADS_SMEM_B);
    k_heads<<<1024, 256, HEADS_SMEM_B>>>(lw, lb, sw, sb, out, pih, piw);
    cudaFuncSetAttribute(k_topk, cudaFuncAttributeMaxDynamicSharedMemorySize, 213504);
    k_topk<<<8, 1024, 212992>>>();   // 4th launch -> ncu capture
    k_mask<<<dim3(94, 24, 8), 256>>>();
    k_nms<<<8, 32>>>(out);
}